// round 8
// baseline (speedup 1.0000x reference)
#include <cuda_runtime.h>
#include <cuda_fp16.h>
#include <stdint.h>

// DAGNNConv: 10-hop normalized propagation + sigmoid-gated combination.
// N=100000, D=64, E=1300000 (incl self-loops), K=10.
// fp16 hop storage; SpMM 4 nodes/warp, 8 lanes/node, LDG.128 gather,
// unconditional (w=0 padded) gathers + pipelined record loads.
// R8: gate fused into the 10th hop (hop-10 result consumed from registers,
// never stored; saves one full pass + one launch).

#define NNODES 100000
#define DIM    64
#define KHOPS  10
#define EMAX   1400000
#define SCAN_B 1024

__device__ int     g_deg[NNODES];
__device__ int     g_fill[NNODES];
__device__ float   g_norm[NNODES];
__device__ int     g_rowoff[NNODES + 1];
__device__ int     g_part[256];
__device__ int2    g_edge[EMAX];                        // {src, bits(w)}
__device__ __half2 g_F16[(size_t)NNODES * 32];          // feats in fp16
__device__ __half2 g_H[(size_t)(KHOPS - 1) * NNODES * 32]; // hops 1..9

// ---------------------------------------------------------------------------
// zero counters + convert feats fp32->fp16 (fused; grid covers NNODES*32)
__global__ void k_zero(const float* __restrict__ feats) {
    int i = blockIdx.x * blockDim.x + threadIdx.x;
    if (i < NNODES) { g_deg[i] = 0; g_fill[i] = 0; }
    if (i < NNODES * 32) {
        float2 f = *(const float2*)(feats + (size_t)i * 2);
        g_F16[i] = __floats2half2_rn(f.x, f.y);
    }
}

__global__ void k_count(const int* __restrict__ dst, int nE) {
    int e = blockIdx.x * blockDim.x + threadIdx.x;
    if (e >= nE) return;
    unsigned d = (unsigned)dst[e];
    if (d < NNODES) atomicAdd(&g_deg[d], 1);
}

__global__ void k_scan1() {
    __shared__ int sh[SCAN_B];
    int idx = blockIdx.x * SCAN_B + threadIdx.x;
    int v = (idx < NNODES) ? g_deg[idx] : 0;
    if (idx < NNODES) g_norm[idx] = rsqrtf((float)v);
    sh[threadIdx.x] = v;
    __syncthreads();
    for (int off = 1; off < SCAN_B; off <<= 1) {
        int t = (threadIdx.x >= off) ? sh[threadIdx.x - off] : 0;
        __syncthreads();
        sh[threadIdx.x] += t;
        __syncthreads();
    }
    int incl = sh[threadIdx.x];
    if (idx < NNODES) g_rowoff[idx] = incl - v;
    if (threadIdx.x == SCAN_B - 1) g_part[blockIdx.x] = incl;
}

__global__ void k_scan2(int nb, int nE) {
    __shared__ int sh[128];
    int v = (threadIdx.x < nb) ? g_part[threadIdx.x] : 0;
    sh[threadIdx.x] = v;
    __syncthreads();
    for (int off = 1; off < 128; off <<= 1) {
        int t = (threadIdx.x >= off) ? sh[threadIdx.x - off] : 0;
        __syncthreads();
        sh[threadIdx.x] += t;
        __syncthreads();
    }
    if (threadIdx.x < nb) g_part[threadIdx.x] = sh[threadIdx.x] - v;
    if (threadIdx.x == 0) g_rowoff[NNODES] = nE;
}

__global__ void k_scan3() {
    int idx = blockIdx.x * SCAN_B + threadIdx.x;
    if (idx < NNODES) g_rowoff[idx] += g_part[blockIdx.x];
}

__global__ void k_scatter(const int* __restrict__ src,
                          const int* __restrict__ dst, int nE) {
    int e = blockIdx.x * blockDim.x + threadIdx.x;
    if (e >= nE) return;
    unsigned s = (unsigned)src[e];
    unsigned d = (unsigned)dst[e];
    if (s >= NNODES || d >= NNODES) return;
    int pos = g_rowoff[d] + atomicAdd(&g_fill[d], 1);
    if (pos < EMAX)
        g_edge[pos] = make_int2((int)s, __float_as_int(g_norm[s] * g_norm[d]));
}

// ---------------------------------------------------------------------------
// SpMM core: returns this lane's 8 fp32 channel accumulators for node v.
__device__ __forceinline__ void spmm_core(
    const uint4* __restrict__ prev, int beg, int deg, int sub, int gb,
    float* a /* [8] */) {
    int maxdeg = deg;
#pragma unroll
    for (int o = 16; o; o >>= 1)
        maxdeg = max(maxdeg, __shfl_xor_sync(0xFFFFFFFFu, maxdeg, o));
    int nbatch = (maxdeg + 7) >> 3;

    int2 er = make_int2(0, 0);
    if (sub < deg) er = g_edge[beg + sub];

    for (int b = 0; b < nbatch; b++) {
        int2 er_next = make_int2(0, 0);
        int nidx = (b + 1) * 8 + sub;
        if (b + 1 < nbatch && nidx < deg) er_next = g_edge[beg + nidx];

        int   srcs[8];
        float ws[8];
#pragma unroll
        for (int j = 0; j < 8; j++) {
            srcs[j] = __shfl_sync(0xFFFFFFFFu, er.x, gb + j);
            ws[j]   = __int_as_float(__shfl_sync(0xFFFFFFFFu, er.y, gb + j));
        }
        uint4 raws[8];
#pragma unroll
        for (int j = 0; j < 8; j++)
            raws[j] = prev[(size_t)srcs[j] * 8 + sub];
#pragma unroll
        for (int j = 0; j < 8; j++) {
            float2 f0 = __half22float2(*(const __half2*)&raws[j].x);
            float2 f1 = __half22float2(*(const __half2*)&raws[j].y);
            float2 f2 = __half22float2(*(const __half2*)&raws[j].z);
            float2 f3 = __half22float2(*(const __half2*)&raws[j].w);
            float w = ws[j];
            a[0] = fmaf(w, f0.x, a[0]); a[1] = fmaf(w, f0.y, a[1]);
            a[2] = fmaf(w, f1.x, a[2]); a[3] = fmaf(w, f1.y, a[3]);
            a[4] = fmaf(w, f2.x, a[4]); a[5] = fmaf(w, f2.y, a[5]);
            a[6] = fmaf(w, f3.x, a[6]); a[7] = fmaf(w, f3.y, a[7]);
        }
        er = er_next;
    }
}

// Hops 0..8: store result fp16.
__global__ void __launch_bounds__(256)
k_spmm(int hop) {
    int warp = blockIdx.x * 8 + (threadIdx.x >> 5);
    int lane = threadIdx.x & 31;
    int sub  = lane & 7;
    int gb   = lane & 24;
    int v    = warp * 4 + (lane >> 3);
    if (v >= NNODES) v = NNODES - 1;

    const uint4* __restrict__ prev = (const uint4*)(
        (hop == 0) ? g_F16 : (g_H + (size_t)(hop - 1) * NNODES * 32));
    uint4* __restrict__ cur = (uint4*)(g_H + (size_t)hop * NNODES * 32);

    int beg = g_rowoff[v];
    int deg = g_rowoff[v + 1] - beg;

    float a[8] = {0.f, 0.f, 0.f, 0.f, 0.f, 0.f, 0.f, 0.f};
    spmm_core(prev, beg, deg, sub, gb, a);

    uint4 o;
    *(__half2*)&o.x = __floats2half2_rn(a[0], a[1]);
    *(__half2*)&o.y = __floats2half2_rn(a[2], a[3]);
    *(__half2*)&o.z = __floats2half2_rn(a[4], a[5]);
    *(__half2*)&o.w = __floats2half2_rn(a[6], a[7]);
    cur[(size_t)v * 8 + sub] = o;
}

// Hop 9 (the 10th) + fused gate. Hop-10 slice consumed from registers.
__global__ void __launch_bounds__(256)
k_spmm_gate(const float* __restrict__ feats, const float* __restrict__ s,
            float* __restrict__ out) {
    int warp = blockIdx.x * 8 + (threadIdx.x >> 5);
    int lane = threadIdx.x & 31;
    int sub  = lane & 7;
    int gb   = lane & 24;
    int v    = warp * 4 + (lane >> 3);
    if (v >= NNODES) v = NNODES - 1;

    const uint4* __restrict__ prev =
        (const uint4*)(g_H + (size_t)(KHOPS - 2) * NNODES * 32);

    int beg = g_rowoff[v];
    int deg = g_rowoff[v + 1] - beg;

    float a[8] = {0.f, 0.f, 0.f, 0.f, 0.f, 0.f, 0.f, 0.f};
    spmm_core(prev, beg, deg, sub, gb, a);   // a = H_10[v], channels sub*8..+7

    // --- gate: lane owns channels [sub*8, sub*8+8) of node v ---
    float4 s0 = *(const float4*)(s + sub * 8);
    float4 s1 = *(const float4*)(s + sub * 8 + 4);

    float acc[8] = {0.f, 0.f, 0.f, 0.f, 0.f, 0.f, 0.f, 0.f};
    float hk[8];

#pragma unroll
    for (int k = 0; k <= KHOPS; k++) {
        if (k == 0) {
            float4 f0 = *(const float4*)(feats + (size_t)v * DIM + sub * 8);
            float4 f1 = *(const float4*)(feats + (size_t)v * DIM + sub * 8 + 4);
            hk[0] = f0.x; hk[1] = f0.y; hk[2] = f0.z; hk[3] = f0.w;
            hk[4] = f1.x; hk[5] = f1.y; hk[6] = f1.z; hk[7] = f1.w;
        } else if (k < KHOPS) {
            uint4 raw = *(const uint4*)(g_H + (size_t)(k - 1) * NNODES * 32 +
                                        (size_t)v * 32 + sub * 4);
            float2 f0 = __half22float2(*(const __half2*)&raw.x);
            float2 f1 = __half22float2(*(const __half2*)&raw.y);
            float2 f2 = __half22float2(*(const __half2*)&raw.z);
            float2 f3 = __half22float2(*(const __half2*)&raw.w);
            hk[0] = f0.x; hk[1] = f0.y; hk[2] = f1.x; hk[3] = f1.y;
            hk[4] = f2.x; hk[5] = f2.y; hk[6] = f3.x; hk[7] = f3.y;
        } else {
#pragma unroll
            for (int c = 0; c < 8; c++) hk[c] = a[c];
        }
        float p = hk[0] * s0.x + hk[1] * s0.y + hk[2] * s0.z + hk[3] * s0.w +
                  hk[4] * s1.x + hk[5] * s1.y + hk[6] * s1.z + hk[7] * s1.w;
        // reduce over the 8 lanes of this group (xor 1,2,4 stays in-group)
        p += __shfl_xor_sync(0xFFFFFFFFu, p, 1);
        p += __shfl_xor_sync(0xFFFFFFFFu, p, 2);
        p += __shfl_xor_sync(0xFFFFFFFFu, p, 4);
        float g = 1.f / (1.f + __expf(-p));
#pragma unroll
        for (int c = 0; c < 8; c++) acc[c] = fmaf(g, hk[c], acc[c]);
    }

    float4 o0, o1;
    o0.x = acc[0]; o0.y = acc[1]; o0.z = acc[2]; o0.w = acc[3];
    o1.x = acc[4]; o1.y = acc[5]; o1.z = acc[6]; o1.w = acc[7];
    *(float4*)(out + (size_t)v * DIM + sub * 8)     = o0;
    *(float4*)(out + (size_t)v * DIM + sub * 8 + 4) = o1;
}

// ---------------------------------------------------------------------------
extern "C" void kernel_launch(void* const* d_in, const int* in_sizes, int n_in,
                              void* d_out, int out_size) {
    const float* feats = (const float*)d_in[0];
    const float* s     = (const float*)d_in[1];
    const int*   src   = (const int*)d_in[2];
    const int*   dst   = (const int*)d_in[3];
    float*       out   = (float*)d_out;
    int nE = in_sizes[2];

    int nb = (NNODES + SCAN_B - 1) / SCAN_B;       // 98
    int eb = (nE + 255) / 256;
    int sb = (NNODES / 4 + 7) / 8;                 // 3125

    k_zero<<<(NNODES * 32 + 255) / 256, 256>>>(feats);
    k_count<<<eb, 256>>>(dst, nE);
    k_scan1<<<nb, SCAN_B>>>();
    k_scan2<<<1, 128>>>(nb, nE);
    k_scan3<<<nb, SCAN_B>>>();
    k_scatter<<<eb, 256>>>(src, dst, nE);

    for (int hop = 0; hop < KHOPS - 1; hop++)
        k_spmm<<<sb, 256>>>(hop);

    k_spmm_gate<<<sb, 256>>>(feats, s, out);
}

// round 9
// speedup vs baseline: 1.5302x; 1.5302x over previous
#include <cuda_runtime.h>
#include <cuda_fp16.h>
#include <stdint.h>

// DAGNNConv: 10-hop normalized propagation + sigmoid-gated combination.
// N=100000, D=64, E=1300000 (incl self-loops), K=10.
// R9: norm factored out of edges (edge record = src int only; hop applies
// norm^2 per node; gate un-scales by 1/norm). Single-launch scan with
// last-block partial scan + lazy g_part add. Hop inner loop identical to R7
// (scalar accumulators, unconditional LDG.128 gathers, pipelined records).

#define NNODES 100000
#define DIM    64
#define KHOPS  10
#define EMAX   1400000
#define SCAN_B 1024

__device__ int     g_deg[NNODES];
__device__ int     g_fill[NNODES];
__device__ float   g_norm[NNODES];
__device__ int     g_rowoff[NNODES + 1];
__device__ int     g_part[128];
__device__ int     g_done;
__device__ int     g_esrc[EMAX];                        // edge src only
__device__ __half2 g_F16[(size_t)NNODES * 32];          // t0 = norm .* feats
__device__ __half2 g_H[(size_t)KHOPS * NNODES * 32];    // t_1..t_10 (scaled)

// ---------------------------------------------------------------------------
__global__ void k_zero() {
    int i = blockIdx.x * blockDim.x + threadIdx.x;
    if (i < NNODES) { g_deg[i] = 0; g_fill[i] = 0; }
    if (i == 0) g_done = 0;
}

__global__ void k_count(const int* __restrict__ dst, int nE) {
    int e = blockIdx.x * blockDim.x + threadIdx.x;
    if (e >= nE) return;
    unsigned d = (unsigned)dst[e];
    if (d < NNODES) atomicAdd(&g_deg[d], 1);
}

// Block-local scan + norm; last-finishing block scans the 98 partials.
// Final rowoff[i] = g_rowoff[i] + g_part[i >> 10] (lazy add by consumers).
__global__ void k_scan(int nb, int nE) {
    __shared__ int sh[SCAN_B];
    __shared__ int amLast;
    int idx = blockIdx.x * SCAN_B + threadIdx.x;
    int v = (idx < NNODES) ? g_deg[idx] : 0;
    if (idx < NNODES) g_norm[idx] = rsqrtf((float)v);
    sh[threadIdx.x] = v;
    __syncthreads();
    for (int off = 1; off < SCAN_B; off <<= 1) {
        int t = (threadIdx.x >= off) ? sh[threadIdx.x - off] : 0;
        __syncthreads();
        sh[threadIdx.x] += t;
        __syncthreads();
    }
    int incl = sh[threadIdx.x];
    if (idx < NNODES) g_rowoff[idx] = incl - v;       // block-local exclusive
    if (threadIdx.x == SCAN_B - 1) g_part[blockIdx.x] = incl;  // block total
    __threadfence();
    __syncthreads();
    if (threadIdx.x == 0)
        amLast = (atomicAdd(&g_done, 1) == nb - 1);
    __syncthreads();
    if (!amLast) return;

    // last block: exclusive-scan the raw partials in place
    int pv = 0;
    if (threadIdx.x < 128) {
        pv = (threadIdx.x < nb) ? g_part[threadIdx.x] : 0;
        sh[threadIdx.x] = pv;
    }
    __syncthreads();
    for (int off = 1; off < 128; off <<= 1) {
        int t = (threadIdx.x >= off && threadIdx.x < 128) ? sh[threadIdx.x - off] : 0;
        __syncthreads();
        if (threadIdx.x < 128) sh[threadIdx.x] += t;
        __syncthreads();
    }
    if (threadIdx.x < 128 && threadIdx.x < nb)
        g_part[threadIdx.x] = sh[threadIdx.x] - pv;   // exclusive offsets
    // rowoff[N] + g_part[N>>10] must equal nE: N>>10 == nb-1, so
    // rowoff[N] = raw partial total of last block = pv at tid nb-1.
    if (threadIdx.x == nb - 1) g_rowoff[NNODES] = pv;
}

// t0 = norm .* feats, stored fp16.
__global__ void k_cvt(const float* __restrict__ feats) {
    int i = blockIdx.x * blockDim.x + threadIdx.x;   // over NNODES*32
    if (i >= NNODES * 32) return;
    float nrm = g_norm[i >> 5];
    float2 f = *(const float2*)(feats + (size_t)i * 2);
    g_F16[i] = __floats2half2_rn(f.x * nrm, f.y * nrm);
}

// Scatter edge sources into CSR (no norm loads needed anymore).
__global__ void k_scatter(const int* __restrict__ src,
                          const int* __restrict__ dst, int nE) {
    int e = blockIdx.x * blockDim.x + threadIdx.x;
    if (e >= nE) return;
    unsigned s = (unsigned)src[e];
    unsigned d = (unsigned)dst[e];
    if (s >= NNODES || d >= NNODES) return;
    int pos = g_rowoff[d] + g_part[d >> 10] + atomicAdd(&g_fill[d], 1);
    if (pos < EMAX) g_esrc[pos] = (int)s;
}

// ---------------------------------------------------------------------------
// One hop: t_cur[v] = norm[v]^2 * sum_{u->v} t_prev[u].
// 4 consecutive nodes per warp; 8 lanes per node; lane owns 8 channels (16B).
// Records: one coalesced int LDG per 8-edge batch, pipelined one batch ahead.
// Gathers unconditional (padded slots read row 0, validity weight 0).
__global__ void __launch_bounds__(256)
k_spmm(int hop) {
    int warp = blockIdx.x * 8 + (threadIdx.x >> 5);
    int lane = threadIdx.x & 31;
    int sub  = lane & 7;
    int gb   = lane & 24;
    int v    = warp * 4 + (lane >> 3);
    if (v >= NNODES) v = NNODES - 1;

    const uint4* __restrict__ prev = (const uint4*)(
        (hop == 0) ? g_F16 : (g_H + (size_t)(hop - 1) * NNODES * 32));
    uint4* __restrict__ cur = (uint4*)(g_H + (size_t)hop * NNODES * 32);

    int beg = g_rowoff[v]     + g_part[v >> 10];
    int end = g_rowoff[v + 1] + g_part[(v + 1) >> 10];
    int deg = end - beg;
    float nrm = g_norm[v];
    float scale = nrm * nrm;

    int maxdeg = deg;
#pragma unroll
    for (int o = 16; o; o >>= 1)
        maxdeg = max(maxdeg, __shfl_xor_sync(0xFFFFFFFFu, maxdeg, o));
    int nbatch = (maxdeg + 7) >> 3;

    float a0 = 0.f, a1 = 0.f, a2 = 0.f, a3 = 0.f;
    float a4 = 0.f, a5 = 0.f, a6 = 0.f, a7 = 0.f;

    int er = (sub < deg) ? g_esrc[beg + sub] : 0;

    for (int b = 0; b < nbatch; b++) {
        int er_next = 0;
        int nidx = (b + 1) * 8 + sub;
        if (b + 1 < nbatch && nidx < deg) er_next = g_esrc[beg + nidx];

        int base = b * 8;
        int srcs[8];
#pragma unroll
        for (int j = 0; j < 8; j++)
            srcs[j] = __shfl_sync(0xFFFFFFFFu, er, gb + j);

        uint4 raws[8];
#pragma unroll
        for (int j = 0; j < 8; j++)
            raws[j] = prev[(size_t)srcs[j] * 8 + sub];
#pragma unroll
        for (int j = 0; j < 8; j++) {
            float w = (base + j < deg) ? 1.f : 0.f;
            float2 f0 = __half22float2(*(const __half2*)&raws[j].x);
            float2 f1 = __half22float2(*(const __half2*)&raws[j].y);
            float2 f2 = __half22float2(*(const __half2*)&raws[j].z);
            float2 f3 = __half22float2(*(const __half2*)&raws[j].w);
            a0 = fmaf(w, f0.x, a0); a1 = fmaf(w, f0.y, a1);
            a2 = fmaf(w, f1.x, a2); a3 = fmaf(w, f1.y, a3);
            a4 = fmaf(w, f2.x, a4); a5 = fmaf(w, f2.y, a5);
            a6 = fmaf(w, f3.x, a6); a7 = fmaf(w, f3.y, a7);
        }
        er = er_next;
    }

    uint4 o;
    *(__half2*)&o.x = __floats2half2_rn(a0 * scale, a1 * scale);
    *(__half2*)&o.y = __floats2half2_rn(a2 * scale, a3 * scale);
    *(__half2*)&o.z = __floats2half2_rn(a4 * scale, a5 * scale);
    *(__half2*)&o.w = __floats2half2_rn(a6 * scale, a7 * scale);
    cur[(size_t)v * 8 + sub] = o;
}

// ---------------------------------------------------------------------------
// Gate + combine. Warp per node; lane owns channels {2*lane, 2*lane+1}.
// Stored slices are t_k = norm .* h_k, so h_k = t_k / norm.
__global__ void __launch_bounds__(256)
k_gate(const float* __restrict__ feats, const float* __restrict__ s,
       float* __restrict__ out) {
    int v = blockIdx.x * 8 + (threadIdx.x >> 5);
    if (v >= NNODES) return;
    int lane = threadIdx.x & 31;

    float2 sv = *(const float2*)(s + 2 * lane);
    float rd = 1.0f / g_norm[v];   // sqrt(deg)

    float2 h[KHOPS + 1];
    h[0] = *(const float2*)(feats + (size_t)v * DIM + 2 * lane);
#pragma unroll
    for (int k = 1; k <= KHOPS; k++) {
        float2 t = __half22float2(
            g_H[(size_t)(k - 1) * NNODES * 32 + (size_t)v * 32 + lane]);
        h[k].x = t.x * rd;
        h[k].y = t.y * rd;
    }

    float a0 = 0.f, a1 = 0.f;
#pragma unroll
    for (int k = 0; k <= KHOPS; k++) {
        float p = h[k].x * sv.x + h[k].y * sv.y;
#pragma unroll
        for (int o = 16; o; o >>= 1) p += __shfl_xor_sync(0xFFFFFFFFu, p, o);
        float g = 1.f / (1.f + __expf(-p));
        a0 = fmaf(g, h[k].x, a0);
        a1 = fmaf(g, h[k].y, a1);
    }
    float2 o2; o2.x = a0; o2.y = a1;
    *(float2*)(out + (size_t)v * DIM + 2 * lane) = o2;
}

// ---------------------------------------------------------------------------
extern "C" void kernel_launch(void* const* d_in, const int* in_sizes, int n_in,
                              void* d_out, int out_size) {
    const float* feats = (const float*)d_in[0];
    const float* s     = (const float*)d_in[1];
    const int*   src   = (const int*)d_in[2];
    const int*   dst   = (const int*)d_in[3];
    float*       out   = (float*)d_out;
    int nE = in_sizes[2];

    int nb = (NNODES + SCAN_B - 1) / SCAN_B;       // 98
    int eb = (nE + 255) / 256;
    int wb = (NNODES + 7) / 8;                     // 12500 (gate)
    int sb = (NNODES / 4 + 7) / 8;                 // 3125  (spmm)

    k_zero<<<(NNODES + 255) / 256, 256>>>();
    k_count<<<eb, 256>>>(dst, nE);
    k_scan<<<nb, SCAN_B>>>(nb, nE);
    k_cvt<<<(NNODES * 32 + 255) / 256, 256>>>(feats);
    k_scatter<<<eb, 256>>>(src, dst, nE);

    for (int hop = 0; hop < KHOPS; hop++)
        k_spmm<<<sb, 256>>>(hop);

    k_gate<<<wb, 256>>>(feats, s, out);
}

// round 10
// speedup vs baseline: 1.5612x; 1.0203x over previous
#include <cuda_runtime.h>
#include <cuda_fp16.h>
#include <stdint.h>

// DAGNNConv: 10-hop normalized propagation + sigmoid-gated combination.
// N=100000, D=64, E=1300000 (incl self-loops), K=10.
// R10: per-block degree rank-sort (32 nodes) so each warp's 4 nodes have
// near-equal degree -> fewer padded gather batches; widened k_cvt.
// Hop inner loop unchanged from R9 (scalar accumulators, unconditional
// LDG.128 gathers, pipelined record loads, norm factored out of edges).

#define NNODES 100000
#define DIM    64
#define KHOPS  10
#define EMAX   1400000
#define SCAN_B 1024

__device__ int     g_deg[NNODES];
__device__ int     g_fill[NNODES];
__device__ float   g_norm[NNODES];
__device__ int     g_rowoff[NNODES + 1];
__device__ int     g_part[128];
__device__ int     g_done;
__device__ int     g_esrc[EMAX];                        // edge src only
__device__ __half2 g_F16[(size_t)NNODES * 32];          // t0 = norm .* feats
__device__ __half2 g_H[(size_t)KHOPS * NNODES * 32];    // t_1..t_10 (scaled)

// ---------------------------------------------------------------------------
__global__ void k_zero() {
    int i = blockIdx.x * blockDim.x + threadIdx.x;
    if (i < NNODES) { g_deg[i] = 0; g_fill[i] = 0; }
    if (i == 0) g_done = 0;
}

__global__ void k_count(const int* __restrict__ dst, int nE) {
    int e = blockIdx.x * blockDim.x + threadIdx.x;
    if (e >= nE) return;
    unsigned d = (unsigned)dst[e];
    if (d < NNODES) atomicAdd(&g_deg[d], 1);
}

// Block-local scan + norm; last-finishing block scans the 98 partials.
// Final rowoff[i] = g_rowoff[i] + g_part[i >> 10] (lazy add by consumers).
__global__ void k_scan(int nb, int nE) {
    __shared__ int sh[SCAN_B];
    __shared__ int amLast;
    int idx = blockIdx.x * SCAN_B + threadIdx.x;
    int v = (idx < NNODES) ? g_deg[idx] : 0;
    if (idx < NNODES) g_norm[idx] = rsqrtf((float)v);
    sh[threadIdx.x] = v;
    __syncthreads();
    for (int off = 1; off < SCAN_B; off <<= 1) {
        int t = (threadIdx.x >= off) ? sh[threadIdx.x - off] : 0;
        __syncthreads();
        sh[threadIdx.x] += t;
        __syncthreads();
    }
    int incl = sh[threadIdx.x];
    if (idx < NNODES) g_rowoff[idx] = incl - v;       // block-local exclusive
    if (threadIdx.x == SCAN_B - 1) g_part[blockIdx.x] = incl;  // block total
    __threadfence();
    __syncthreads();
    if (threadIdx.x == 0)
        amLast = (atomicAdd(&g_done, 1) == nb - 1);
    __syncthreads();
    if (!amLast) return;

    int pv = 0;
    if (threadIdx.x < 128) {
        pv = (threadIdx.x < nb) ? g_part[threadIdx.x] : 0;
        sh[threadIdx.x] = pv;
    }
    __syncthreads();
    for (int off = 1; off < 128; off <<= 1) {
        int t = (threadIdx.x >= off && threadIdx.x < 128) ? sh[threadIdx.x - off] : 0;
        __syncthreads();
        if (threadIdx.x < 128) sh[threadIdx.x] += t;
        __syncthreads();
    }
    if (threadIdx.x < 128 && threadIdx.x < nb)
        g_part[threadIdx.x] = sh[threadIdx.x] - pv;   // exclusive offsets
    if (threadIdx.x == nb - 1) g_rowoff[NNODES] = pv;
}

// t0 = norm .* feats, stored fp16; wide: thread handles 8 channels.
__global__ void k_cvt(const float* __restrict__ feats) {
    int i = blockIdx.x * blockDim.x + threadIdx.x;   // over NNODES*8
    if (i >= NNODES * 8) return;
    float nrm = g_norm[i >> 3];
    float4 f0 = *(const float4*)(feats + (size_t)i * 8);
    float4 f1 = *(const float4*)(feats + (size_t)i * 8 + 4);
    uint4 o;
    *(__half2*)&o.x = __floats2half2_rn(f0.x * nrm, f0.y * nrm);
    *(__half2*)&o.y = __floats2half2_rn(f0.z * nrm, f0.w * nrm);
    *(__half2*)&o.z = __floats2half2_rn(f1.x * nrm, f1.y * nrm);
    *(__half2*)&o.w = __floats2half2_rn(f1.z * nrm, f1.w * nrm);
    ((uint4*)g_F16)[i] = o;
}

__global__ void k_scatter(const int* __restrict__ src,
                          const int* __restrict__ dst, int nE) {
    int e = blockIdx.x * blockDim.x + threadIdx.x;
    if (e >= nE) return;
    unsigned s = (unsigned)src[e];
    unsigned d = (unsigned)dst[e];
    if (s >= NNODES || d >= NNODES) return;
    int pos = g_rowoff[d] + g_part[d >> 10] + atomicAdd(&g_fill[d], 1);
    if (pos < EMAX) g_esrc[pos] = (int)s;
}

// ---------------------------------------------------------------------------
// One hop: t_cur[v] = norm[v]^2 * sum_{u->v} t_prev[u].
// Block owns 32 consecutive nodes; they are rank-sorted by degree in smem so
// each warp's 4 nodes have near-equal degree. 8 lanes per node; lane owns 8
// channels (16B). Records pipelined; gathers unconditional (w=0 padding).
__global__ void __launch_bounds__(256)
k_spmm(int hop) {
    __shared__ int sbeg[32], sdeg[32], sperm[32];
    int tid = threadIdx.x;
    int blockBase = blockIdx.x * 32;

    if (tid < 32) {
        int v = blockBase + tid;
        if (v >= NNODES) v = NNODES - 1;
        int b = g_rowoff[v]     + g_part[v >> 10];
        int e = g_rowoff[v + 1] + g_part[(v + 1) >> 10];
        sbeg[tid] = b;
        sdeg[tid] = e - b;
    }
    __syncthreads();
    if (tid < 32) {
        int d = sdeg[tid];
        int r = 0;
#pragma unroll
        for (int j = 0; j < 32; j++) {
            int dj = sdeg[j];
            r += (dj > d) || (dj == d && j < tid);
        }
        sperm[r] = tid;   // descending degree
    }
    __syncthreads();

    int lane = tid & 31;
    int sub  = lane & 7;
    int gb   = lane & 24;
    int slot = (tid >> 5) * 4 + (lane >> 3);
    int local = sperm[slot];
    int v = blockBase + local;
    if (v >= NNODES) v = NNODES - 1;
    int beg = sbeg[local];
    int deg = sdeg[local];

    const uint4* __restrict__ prev = (const uint4*)(
        (hop == 0) ? g_F16 : (g_H + (size_t)(hop - 1) * NNODES * 32));
    uint4* __restrict__ cur = (uint4*)(g_H + (size_t)hop * NNODES * 32);

    float nrm = g_norm[v];
    float scale = nrm * nrm;

    int maxdeg = deg;
#pragma unroll
    for (int o = 16; o; o >>= 1)
        maxdeg = max(maxdeg, __shfl_xor_sync(0xFFFFFFFFu, maxdeg, o));
    int nbatch = (maxdeg + 7) >> 3;

    float a0 = 0.f, a1 = 0.f, a2 = 0.f, a3 = 0.f;
    float a4 = 0.f, a5 = 0.f, a6 = 0.f, a7 = 0.f;

    int er = (sub < deg) ? g_esrc[beg + sub] : 0;

    for (int b = 0; b < nbatch; b++) {
        int er_next = 0;
        int nidx = (b + 1) * 8 + sub;
        if (b + 1 < nbatch && nidx < deg) er_next = g_esrc[beg + nidx];

        int base = b * 8;
        int srcs[8];
#pragma unroll
        for (int j = 0; j < 8; j++)
            srcs[j] = __shfl_sync(0xFFFFFFFFu, er, gb + j);

        uint4 raws[8];
#pragma unroll
        for (int j = 0; j < 8; j++)
            raws[j] = prev[(size_t)srcs[j] * 8 + sub];
#pragma unroll
        for (int j = 0; j < 8; j++) {
            float w = (base + j < deg) ? 1.f : 0.f;
            float2 f0 = __half22float2(*(const __half2*)&raws[j].x);
            float2 f1 = __half22float2(*(const __half2*)&raws[j].y);
            float2 f2 = __half22float2(*(const __half2*)&raws[j].z);
            float2 f3 = __half22float2(*(const __half2*)&raws[j].w);
            a0 = fmaf(w, f0.x, a0); a1 = fmaf(w, f0.y, a1);
            a2 = fmaf(w, f1.x, a2); a3 = fmaf(w, f1.y, a3);
            a4 = fmaf(w, f2.x, a4); a5 = fmaf(w, f2.y, a5);
            a6 = fmaf(w, f3.x, a6); a7 = fmaf(w, f3.y, a7);
        }
        er = er_next;
    }

    uint4 o;
    *(__half2*)&o.x = __floats2half2_rn(a0 * scale, a1 * scale);
    *(__half2*)&o.y = __floats2half2_rn(a2 * scale, a3 * scale);
    *(__half2*)&o.z = __floats2half2_rn(a4 * scale, a5 * scale);
    *(__half2*)&o.w = __floats2half2_rn(a6 * scale, a7 * scale);
    cur[(size_t)v * 8 + sub] = o;
}

// ---------------------------------------------------------------------------
// Gate + combine. Warp per node; lane owns channels {2*lane, 2*lane+1}.
// Stored slices are t_k = norm .* h_k, so h_k = t_k / norm.
__global__ void __launch_bounds__(256)
k_gate(const float* __restrict__ feats, const float* __restrict__ s,
       float* __restrict__ out) {
    int v = blockIdx.x * 8 + (threadIdx.x >> 5);
    if (v >= NNODES) return;
    int lane = threadIdx.x & 31;

    float2 sv = *(const float2*)(s + 2 * lane);
    float rd = 1.0f / g_norm[v];   // sqrt(deg)

    float2 h[KHOPS + 1];
    h[0] = *(const float2*)(feats + (size_t)v * DIM + 2 * lane);
#pragma unroll
    for (int k = 1; k <= KHOPS; k++) {
        float2 t = __half22float2(
            g_H[(size_t)(k - 1) * NNODES * 32 + (size_t)v * 32 + lane]);
        h[k].x = t.x * rd;
        h[k].y = t.y * rd;
    }

    float a0 = 0.f, a1 = 0.f;
#pragma unroll
    for (int k = 0; k <= KHOPS; k++) {
        float p = h[k].x * sv.x + h[k].y * sv.y;
#pragma unroll
        for (int o = 16; o; o >>= 1) p += __shfl_xor_sync(0xFFFFFFFFu, p, o);
        float g = 1.f / (1.f + __expf(-p));
        a0 = fmaf(g, h[k].x, a0);
        a1 = fmaf(g, h[k].y, a1);
    }
    float2 o2; o2.x = a0; o2.y = a1;
    *(float2*)(out + (size_t)v * DIM + 2 * lane) = o2;
}

// ---------------------------------------------------------------------------
extern "C" void kernel_launch(void* const* d_in, const int* in_sizes, int n_in,
                              void* d_out, int out_size) {
    const float* feats = (const float*)d_in[0];
    const float* s     = (const float*)d_in[1];
    const int*   src   = (const int*)d_in[2];
    const int*   dst   = (const int*)d_in[3];
    float*       out   = (float*)d_out;
    int nE = in_sizes[2];

    int nb = (NNODES + SCAN_B - 1) / SCAN_B;       // 98
    int eb = (nE + 255) / 256;
    int wb = (NNODES + 7) / 8;                     // 12500 (gate)
    int sb = (NNODES + 31) / 32;                   // 3125  (spmm)

    k_zero<<<(NNODES + 255) / 256, 256>>>();
    k_count<<<eb, 256>>>(dst, nE);
    k_scan<<<nb, SCAN_B>>>(nb, nE);
    k_cvt<<<(NNODES * 8 + 255) / 256, 256>>>(feats);
    k_scatter<<<eb, 256>>>(src, dst, nE);

    for (int hop = 0; hop < KHOPS; hop++)
        k_spmm<<<sb, 256>>>(hop);

    k_gate<<<wb, 256>>>(feats, s, out);
}

// round 11
// speedup vs baseline: 1.5853x; 1.0154x over previous
#include <cuda_runtime.h>
#include <cuda_fp16.h>
#include <stdint.h>

// DAGNNConv: 10-hop normalized propagation + sigmoid-gated combination.
// N=100000, D=64, E=1300000 (incl self-loops), K=10.
// R11: cvt fused into scan; gate rewritten in 8-lane-group uint4 layout
// (h0 read from fp16 t0); count vectorized int4. Hop kernel unchanged
// (per-block degree rank-sort, scalar accumulators, unconditional LDG.128
// gathers, pipelined records, norm factored out of edges).

#define NNODES 100000
#define DIM    64
#define KHOPS  10
#define EMAX   1400000
#define SCAN_B 1024

__device__ int     g_deg[NNODES];
__device__ int     g_fill[NNODES];
__device__ float   g_norm[NNODES];
__device__ int     g_rowoff[NNODES + 1];
__device__ int     g_part[128];
__device__ int     g_done;
__device__ int     g_esrc[EMAX];                        // edge src only
__device__ __half2 g_F16[(size_t)NNODES * 32];          // t0 = norm .* feats
__device__ __half2 g_H[(size_t)KHOPS * NNODES * 32];    // t_1..t_10 (scaled)

// ---------------------------------------------------------------------------
__global__ void k_zero() {
    int i = blockIdx.x * blockDim.x + threadIdx.x;
    if (i < NNODES) { g_deg[i] = 0; g_fill[i] = 0; }
    if (i == 0) g_done = 0;
}

// int4-vectorized degree count (nE divisible by 4 handled with tail guard).
__global__ void k_count(const int* __restrict__ dst, int nE) {
    int q = blockIdx.x * blockDim.x + threadIdx.x;
    int nq = nE >> 2;
    if (q < nq) {
        int4 d4 = ((const int4*)dst)[q];
        if ((unsigned)d4.x < NNODES) atomicAdd(&g_deg[d4.x], 1);
        if ((unsigned)d4.y < NNODES) atomicAdd(&g_deg[d4.y], 1);
        if ((unsigned)d4.z < NNODES) atomicAdd(&g_deg[d4.z], 1);
        if ((unsigned)d4.w < NNODES) atomicAdd(&g_deg[d4.w], 1);
    } else if (q == nq) {
        for (int e = nq * 4; e < nE; e++) {
            unsigned d = (unsigned)dst[e];
            if (d < NNODES) atomicAdd(&g_deg[d], 1);
        }
    }
}

// Block-local scan + norm + fp16 convert of this block's nodes; the
// last-finishing block scans the 98 partials.
// Final rowoff[i] = g_rowoff[i] + g_part[i >> 10] (lazy add by consumers).
__global__ void k_scan(const float* __restrict__ feats, int nb, int nE) {
    __shared__ int sh[SCAN_B];
    __shared__ int amLast;
    int idx = blockIdx.x * SCAN_B + threadIdx.x;
    int v = (idx < NNODES) ? g_deg[idx] : 0;
    float nrm = rsqrtf((float)v);
    if (idx < NNODES) g_norm[idx] = nrm;
    sh[threadIdx.x] = v;
    __syncthreads();
    for (int off = 1; off < SCAN_B; off <<= 1) {
        int t = (threadIdx.x >= off) ? sh[threadIdx.x - off] : 0;
        __syncthreads();
        sh[threadIdx.x] += t;
        __syncthreads();
    }
    int incl = sh[threadIdx.x];
    if (idx < NNODES) g_rowoff[idx] = incl - v;       // block-local exclusive
    if (threadIdx.x == SCAN_B - 1) g_part[blockIdx.x] = incl;  // block total

    // fp16 convert this block's 1024 nodes (coalesced: 8 uint4 per thread)
    {
        int nodeBase = blockIdx.x * SCAN_B;
#pragma unroll
        for (int c = 0; c < 8; c++) {
            int i = nodeBase * 8 + c * SCAN_B + threadIdx.x;  // uint4 index
            if (i < NNODES * 8) {
                float nv = g_norm[i >> 3];
                float4 f0 = *(const float4*)(feats + (size_t)i * 8);
                float4 f1 = *(const float4*)(feats + (size_t)i * 8 + 4);
                uint4 o;
                *(__half2*)&o.x = __floats2half2_rn(f0.x * nv, f0.y * nv);
                *(__half2*)&o.y = __floats2half2_rn(f0.z * nv, f0.w * nv);
                *(__half2*)&o.z = __floats2half2_rn(f1.x * nv, f1.y * nv);
                *(__half2*)&o.w = __floats2half2_rn(f1.z * nv, f1.w * nv);
                ((uint4*)g_F16)[i] = o;
            }
        }
    }

    __threadfence();
    __syncthreads();
    if (threadIdx.x == 0)
        amLast = (atomicAdd(&g_done, 1) == nb - 1);
    __syncthreads();
    if (!amLast) return;

    int pv = 0;
    if (threadIdx.x < 128) {
        pv = (threadIdx.x < nb) ? g_part[threadIdx.x] : 0;
        sh[threadIdx.x] = pv;
    }
    __syncthreads();
    for (int off = 1; off < 128; off <<= 1) {
        int t = (threadIdx.x >= off && threadIdx.x < 128) ? sh[threadIdx.x - off] : 0;
        __syncthreads();
        if (threadIdx.x < 128) sh[threadIdx.x] += t;
        __syncthreads();
    }
    if (threadIdx.x < 128 && threadIdx.x < nb)
        g_part[threadIdx.x] = sh[threadIdx.x] - pv;   // exclusive offsets
    if (threadIdx.x == nb - 1) g_rowoff[NNODES] = pv;
}

__global__ void k_scatter(const int* __restrict__ src,
                          const int* __restrict__ dst, int nE) {
    int e = blockIdx.x * blockDim.x + threadIdx.x;
    if (e >= nE) return;
    unsigned s = (unsigned)src[e];
    unsigned d = (unsigned)dst[e];
    if (s >= NNODES || d >= NNODES) return;
    int pos = g_rowoff[d] + g_part[d >> 10] + atomicAdd(&g_fill[d], 1);
    if (pos < EMAX) g_esrc[pos] = (int)s;
}

// ---------------------------------------------------------------------------
// One hop: t_cur[v] = norm[v]^2 * sum_{u->v} t_prev[u].
// Block owns 32 consecutive nodes, rank-sorted by degree in smem; each warp
// takes 4 rank-adjacent nodes; 8 lanes/node; lane owns 8 channels (16B).
__global__ void __launch_bounds__(256)
k_spmm(int hop) {
    __shared__ int sbeg[32], sdeg[32], sperm[32];
    int tid = threadIdx.x;
    int blockBase = blockIdx.x * 32;

    if (tid < 32) {
        int v = blockBase + tid;
        if (v >= NNODES) v = NNODES - 1;
        int b = g_rowoff[v]     + g_part[v >> 10];
        int e = g_rowoff[v + 1] + g_part[(v + 1) >> 10];
        sbeg[tid] = b;
        sdeg[tid] = e - b;
    }
    __syncthreads();
    if (tid < 32) {
        int d = sdeg[tid];
        int r = 0;
#pragma unroll
        for (int j = 0; j < 32; j++) {
            int dj = sdeg[j];
            r += (dj > d) || (dj == d && j < tid);
        }
        sperm[r] = tid;   // descending degree
    }
    __syncthreads();

    int lane = tid & 31;
    int sub  = lane & 7;
    int gb   = lane & 24;
    int slot = (tid >> 5) * 4 + (lane >> 3);
    int local = sperm[slot];
    int v = blockBase + local;
    if (v >= NNODES) v = NNODES - 1;
    int beg = sbeg[local];
    int deg = sdeg[local];

    const uint4* __restrict__ prev = (const uint4*)(
        (hop == 0) ? g_F16 : (g_H + (size_t)(hop - 1) * NNODES * 32));
    uint4* __restrict__ cur = (uint4*)(g_H + (size_t)hop * NNODES * 32);

    float nrm = g_norm[v];
    float scale = nrm * nrm;

    int maxdeg = deg;
#pragma unroll
    for (int o = 16; o; o >>= 1)
        maxdeg = max(maxdeg, __shfl_xor_sync(0xFFFFFFFFu, maxdeg, o));
    int nbatch = (maxdeg + 7) >> 3;

    float a0 = 0.f, a1 = 0.f, a2 = 0.f, a3 = 0.f;
    float a4 = 0.f, a5 = 0.f, a6 = 0.f, a7 = 0.f;

    int er = (sub < deg) ? g_esrc[beg + sub] : 0;

    for (int b = 0; b < nbatch; b++) {
        int er_next = 0;
        int nidx = (b + 1) * 8 + sub;
        if (b + 1 < nbatch && nidx < deg) er_next = g_esrc[beg + nidx];

        int base = b * 8;
        int srcs[8];
#pragma unroll
        for (int j = 0; j < 8; j++)
            srcs[j] = __shfl_sync(0xFFFFFFFFu, er, gb + j);

        uint4 raws[8];
#pragma unroll
        for (int j = 0; j < 8; j++)
            raws[j] = prev[(size_t)srcs[j] * 8 + sub];
#pragma unroll
        for (int j = 0; j < 8; j++) {
            float w = (base + j < deg) ? 1.f : 0.f;
            float2 f0 = __half22float2(*(const __half2*)&raws[j].x);
            float2 f1 = __half22float2(*(const __half2*)&raws[j].y);
            float2 f2 = __half22float2(*(const __half2*)&raws[j].z);
            float2 f3 = __half22float2(*(const __half2*)&raws[j].w);
            a0 = fmaf(w, f0.x, a0); a1 = fmaf(w, f0.y, a1);
            a2 = fmaf(w, f1.x, a2); a3 = fmaf(w, f1.y, a3);
            a4 = fmaf(w, f2.x, a4); a5 = fmaf(w, f2.y, a5);
            a6 = fmaf(w, f3.x, a6); a7 = fmaf(w, f3.y, a7);
        }
        er = er_next;
    }

    uint4 o;
    *(__half2*)&o.x = __floats2half2_rn(a0 * scale, a1 * scale);
    *(__half2*)&o.y = __floats2half2_rn(a2 * scale, a3 * scale);
    *(__half2*)&o.z = __floats2half2_rn(a4 * scale, a5 * scale);
    *(__half2*)&o.w = __floats2half2_rn(a6 * scale, a7 * scale);
    cur[(size_t)v * 8 + sub] = o;
}

// ---------------------------------------------------------------------------
// Gate + combine, 8-lane-group layout: 4 nodes/warp, lane owns channels
// [sub*8, sub*8+8). All slices (incl. h0 from g_F16) read as uint4.
// Stored slices are t_k = norm .* h_k, so h_k = t_k / norm.
__global__ void __launch_bounds__(256)
k_gate(const float* __restrict__ s, float* __restrict__ out) {
    int warp = blockIdx.x * 8 + (threadIdx.x >> 5);
    int lane = threadIdx.x & 31;
    int sub  = lane & 7;
    int v    = warp * 4 + (lane >> 3);
    if (v >= NNODES) v = NNODES - 1;

    float rd = 1.0f / g_norm[v];   // sqrt(deg); h_k = t_k * rd (incl. k=0)

    float4 s0 = *(const float4*)(s + sub * 8);
    float4 s1 = *(const float4*)(s + sub * 8 + 4);

    float acc[8] = {0.f, 0.f, 0.f, 0.f, 0.f, 0.f, 0.f, 0.f};

#pragma unroll
    for (int k = 0; k <= KHOPS; k++) {
        const uint4* slice = (const uint4*)(
            (k == 0) ? g_F16 : (g_H + (size_t)(k - 1) * NNODES * 32));
        uint4 raw = slice[(size_t)v * 8 + sub];
        float2 f0 = __half22float2(*(const __half2*)&raw.x);
        float2 f1 = __half22float2(*(const __half2*)&raw.y);
        float2 f2 = __half22float2(*(const __half2*)&raw.z);
        float2 f3 = __half22float2(*(const __half2*)&raw.w);
        float hk[8];
        hk[0] = f0.x * rd; hk[1] = f0.y * rd;
        hk[2] = f1.x * rd; hk[3] = f1.y * rd;
        hk[4] = f2.x * rd; hk[5] = f2.y * rd;
        hk[6] = f3.x * rd; hk[7] = f3.y * rd;

        float p = hk[0] * s0.x + hk[1] * s0.y + hk[2] * s0.z + hk[3] * s0.w +
                  hk[4] * s1.x + hk[5] * s1.y + hk[6] * s1.z + hk[7] * s1.w;
        p += __shfl_xor_sync(0xFFFFFFFFu, p, 1);
        p += __shfl_xor_sync(0xFFFFFFFFu, p, 2);
        p += __shfl_xor_sync(0xFFFFFFFFu, p, 4);
        float g = 1.f / (1.f + __expf(-p));
#pragma unroll
        for (int c = 0; c < 8; c++) acc[c] = fmaf(g, hk[c], acc[c]);
    }

    float4 o0, o1;
    o0.x = acc[0]; o0.y = acc[1]; o0.z = acc[2]; o0.w = acc[3];
    o1.x = acc[4]; o1.y = acc[5]; o1.z = acc[6]; o1.w = acc[7];
    *(float4*)(out + (size_t)v * DIM + sub * 8)     = o0;
    *(float4*)(out + (size_t)v * DIM + sub * 8 + 4) = o1;
}

// ---------------------------------------------------------------------------
extern "C" void kernel_launch(void* const* d_in, const int* in_sizes, int n_in,
                              void* d_out, int out_size) {
    const float* feats = (const float*)d_in[0];
    const float* s     = (const float*)d_in[1];
    const int*   src   = (const int*)d_in[2];
    const int*   dst   = (const int*)d_in[3];
    float*       out   = (float*)d_out;
    int nE = in_sizes[2];

    int nb = (NNODES + SCAN_B - 1) / SCAN_B;       // 98
    int eb = (nE + 255) / 256;
    int qb = (nE / 4 + 256) / 256;
    int sb = (NNODES + 31) / 32;                   // 3125

    k_zero<<<(NNODES + 255) / 256, 256>>>();
    k_count<<<qb, 256>>>(dst, nE);
    k_scan<<<nb, SCAN_B>>>(feats, nb, nE);
    k_scatter<<<eb, 256>>>(src, dst, nE);

    for (int hop = 0; hop < KHOPS; hop++)
        k_spmm<<<sb, 256>>>(hop);

    k_gate<<<sb, 256>>>(s, out);
}

// round 12
// speedup vs baseline: 1.6022x; 1.0107x over previous
#include <cuda_runtime.h>
#include <cuda_fp16.h>
#include <stdint.h>

// DAGNNConv: 10-hop normalized propagation + sigmoid-gated combination.
// N=100000, D=64, E=1300000 (incl self-loops), K=10.
// R12: atomic-free scatter — k_count's atomicAdd return value IS the edge's
// rank within its CSR row; store it and scatter becomes one random store.
// Everything else unchanged from R11.

#define NNODES 100000
#define DIM    64
#define KHOPS  10
#define EMAX   1400000
#define SCAN_B 1024

__device__ int     g_deg[NNODES];
__device__ float   g_norm[NNODES];
__device__ int     g_rowoff[NNODES + 1];
__device__ int     g_part[128];
__device__ int     g_done;
__device__ int     g_rank[EMAX];                        // edge rank in its row
__device__ int     g_esrc[EMAX];                        // edge src only (CSR)
__device__ __half2 g_F16[(size_t)NNODES * 32];          // t0 = norm .* feats
__device__ __half2 g_H[(size_t)KHOPS * NNODES * 32];    // t_1..t_10 (scaled)

// ---------------------------------------------------------------------------
__global__ void k_zero() {
    int i = blockIdx.x * blockDim.x + threadIdx.x;
    if (i < NNODES) g_deg[i] = 0;
    if (i == 0) g_done = 0;
}

// int4-vectorized degree count; atomic return value = edge rank in row.
__global__ void k_count(const int* __restrict__ dst, int nE) {
    int q = blockIdx.x * blockDim.x + threadIdx.x;
    int nq = nE >> 2;
    if (q < nq) {
        int4 d4 = ((const int4*)dst)[q];
        int4 r4;
        r4.x = ((unsigned)d4.x < NNODES) ? atomicAdd(&g_deg[d4.x], 1) : 0;
        r4.y = ((unsigned)d4.y < NNODES) ? atomicAdd(&g_deg[d4.y], 1) : 0;
        r4.z = ((unsigned)d4.z < NNODES) ? atomicAdd(&g_deg[d4.z], 1) : 0;
        r4.w = ((unsigned)d4.w < NNODES) ? atomicAdd(&g_deg[d4.w], 1) : 0;
        ((int4*)g_rank)[q] = r4;
    } else if (q == nq) {
        for (int e = nq * 4; e < nE; e++) {
            unsigned d = (unsigned)dst[e];
            g_rank[e] = (d < NNODES) ? atomicAdd(&g_deg[d], 1) : 0;
        }
    }
}

// Block-local scan + norm + fp16 convert of this block's nodes; the
// last-finishing block scans the 98 partials.
// Final rowoff[i] = g_rowoff[i] + g_part[i >> 10] (lazy add by consumers).
__global__ void k_scan(const float* __restrict__ feats, int nb, int nE) {
    __shared__ int sh[SCAN_B];
    __shared__ int amLast;
    int idx = blockIdx.x * SCAN_B + threadIdx.x;
    int v = (idx < NNODES) ? g_deg[idx] : 0;
    float nrm = rsqrtf((float)v);
    if (idx < NNODES) g_norm[idx] = nrm;
    sh[threadIdx.x] = v;
    __syncthreads();
    for (int off = 1; off < SCAN_B; off <<= 1) {
        int t = (threadIdx.x >= off) ? sh[threadIdx.x - off] : 0;
        __syncthreads();
        sh[threadIdx.x] += t;
        __syncthreads();
    }
    int incl = sh[threadIdx.x];
    if (idx < NNODES) g_rowoff[idx] = incl - v;       // block-local exclusive
    if (threadIdx.x == SCAN_B - 1) g_part[blockIdx.x] = incl;  // block total

    // fp16 convert this block's 1024 nodes (coalesced: 8 uint4 per thread)
    {
        int nodeBase = blockIdx.x * SCAN_B;
#pragma unroll
        for (int c = 0; c < 8; c++) {
            int i = nodeBase * 8 + c * SCAN_B + threadIdx.x;  // uint4 index
            if (i < NNODES * 8) {
                float nv = g_norm[i >> 3];
                float4 f0 = *(const float4*)(feats + (size_t)i * 8);
                float4 f1 = *(const float4*)(feats + (size_t)i * 8 + 4);
                uint4 o;
                *(__half2*)&o.x = __floats2half2_rn(f0.x * nv, f0.y * nv);
                *(__half2*)&o.y = __floats2half2_rn(f0.z * nv, f0.w * nv);
                *(__half2*)&o.z = __floats2half2_rn(f1.x * nv, f1.y * nv);
                *(__half2*)&o.w = __floats2half2_rn(f1.z * nv, f1.w * nv);
                ((uint4*)g_F16)[i] = o;
            }
        }
    }

    __threadfence();
    __syncthreads();
    if (threadIdx.x == 0)
        amLast = (atomicAdd(&g_done, 1) == nb - 1);
    __syncthreads();
    if (!amLast) return;

    int pv = 0;
    if (threadIdx.x < 128) {
        pv = (threadIdx.x < nb) ? g_part[threadIdx.x] : 0;
        sh[threadIdx.x] = pv;
    }
    __syncthreads();
    for (int off = 1; off < 128; off <<= 1) {
        int t = (threadIdx.x >= off && threadIdx.x < 128) ? sh[threadIdx.x - off] : 0;
        __syncthreads();
        if (threadIdx.x < 128) sh[threadIdx.x] += t;
        __syncthreads();
    }
    if (threadIdx.x < 128 && threadIdx.x < nb)
        g_part[threadIdx.x] = sh[threadIdx.x] - pv;   // exclusive offsets
    if (threadIdx.x == nb - 1) g_rowoff[NNODES] = pv;
}

// Atomic-free scatter: pos = rowoff[d] + part + rank (all loads coalesced).
__global__ void k_scatter(const int* __restrict__ src,
                          const int* __restrict__ dst, int nE) {
    int q = blockIdx.x * blockDim.x + threadIdx.x;
    int nq = nE >> 2;
    if (q < nq) {
        int4 s4 = ((const int4*)src)[q];
        int4 d4 = ((const int4*)dst)[q];
        int4 r4 = ((const int4*)g_rank)[q];
        if ((unsigned)s4.x < NNODES && (unsigned)d4.x < NNODES)
            g_esrc[g_rowoff[d4.x] + g_part[d4.x >> 10] + r4.x] = s4.x;
        if ((unsigned)s4.y < NNODES && (unsigned)d4.y < NNODES)
            g_esrc[g_rowoff[d4.y] + g_part[d4.y >> 10] + r4.y] = s4.y;
        if ((unsigned)s4.z < NNODES && (unsigned)d4.z < NNODES)
            g_esrc[g_rowoff[d4.z] + g_part[d4.z >> 10] + r4.z] = s4.z;
        if ((unsigned)s4.w < NNODES && (unsigned)d4.w < NNODES)
            g_esrc[g_rowoff[d4.w] + g_part[d4.w >> 10] + r4.w] = s4.w;
    } else if (q == nq) {
        for (int e = nq * 4; e < nE; e++) {
            unsigned s = (unsigned)src[e];
            unsigned d = (unsigned)dst[e];
            if (s < NNODES && d < NNODES)
                g_esrc[g_rowoff[d] + g_part[d >> 10] + g_rank[e]] = (int)s;
        }
    }
}

// ---------------------------------------------------------------------------
// One hop: t_cur[v] = norm[v]^2 * sum_{u->v} t_prev[u].
// Block owns 32 consecutive nodes, rank-sorted by degree in smem; each warp
// takes 4 rank-adjacent nodes; 8 lanes/node; lane owns 8 channels (16B).
__global__ void __launch_bounds__(256)
k_spmm(int hop) {
    __shared__ int sbeg[32], sdeg[32], sperm[32];
    int tid = threadIdx.x;
    int blockBase = blockIdx.x * 32;

    if (tid < 32) {
        int v = blockBase + tid;
        if (v >= NNODES) v = NNODES - 1;
        int b = g_rowoff[v]     + g_part[v >> 10];
        int e = g_rowoff[v + 1] + g_part[(v + 1) >> 10];
        sbeg[tid] = b;
        sdeg[tid] = e - b;
    }
    __syncthreads();
    if (tid < 32) {
        int d = sdeg[tid];
        int r = 0;
#pragma unroll
        for (int j = 0; j < 32; j++) {
            int dj = sdeg[j];
            r += (dj > d) || (dj == d && j < tid);
        }
        sperm[r] = tid;   // descending degree
    }
    __syncthreads();

    int lane = tid & 31;
    int sub  = lane & 7;
    int gb   = lane & 24;
    int slot = (tid >> 5) * 4 + (lane >> 3);
    int local = sperm[slot];
    int v = blockBase + local;
    if (v >= NNODES) v = NNODES - 1;
    int beg = sbeg[local];
    int deg = sdeg[local];

    const uint4* __restrict__ prev = (const uint4*)(
        (hop == 0) ? g_F16 : (g_H + (size_t)(hop - 1) * NNODES * 32));
    uint4* __restrict__ cur = (uint4*)(g_H + (size_t)hop * NNODES * 32);

    float nrm = g_norm[v];
    float scale = nrm * nrm;

    int maxdeg = deg;
#pragma unroll
    for (int o = 16; o; o >>= 1)
        maxdeg = max(maxdeg, __shfl_xor_sync(0xFFFFFFFFu, maxdeg, o));
    int nbatch = (maxdeg + 7) >> 3;

    float a0 = 0.f, a1 = 0.f, a2 = 0.f, a3 = 0.f;
    float a4 = 0.f, a5 = 0.f, a6 = 0.f, a7 = 0.f;

    int er = (sub < deg) ? g_esrc[beg + sub] : 0;

    for (int b = 0; b < nbatch; b++) {
        int er_next = 0;
        int nidx = (b + 1) * 8 + sub;
        if (b + 1 < nbatch && nidx < deg) er_next = g_esrc[beg + nidx];

        int base = b * 8;
        int srcs[8];
#pragma unroll
        for (int j = 0; j < 8; j++)
            srcs[j] = __shfl_sync(0xFFFFFFFFu, er, gb + j);

        uint4 raws[8];
#pragma unroll
        for (int j = 0; j < 8; j++)
            raws[j] = prev[(size_t)srcs[j] * 8 + sub];
#pragma unroll
        for (int j = 0; j < 8; j++) {
            float w = (base + j < deg) ? 1.f : 0.f;
            float2 f0 = __half22float2(*(const __half2*)&raws[j].x);
            float2 f1 = __half22float2(*(const __half2*)&raws[j].y);
            float2 f2 = __half22float2(*(const __half2*)&raws[j].z);
            float2 f3 = __half22float2(*(const __half2*)&raws[j].w);
            a0 = fmaf(w, f0.x, a0); a1 = fmaf(w, f0.y, a1);
            a2 = fmaf(w, f1.x, a2); a3 = fmaf(w, f1.y, a3);
            a4 = fmaf(w, f2.x, a4); a5 = fmaf(w, f2.y, a5);
            a6 = fmaf(w, f3.x, a6); a7 = fmaf(w, f3.y, a7);
        }
        er = er_next;
    }

    uint4 o;
    *(__half2*)&o.x = __floats2half2_rn(a0 * scale, a1 * scale);
    *(__half2*)&o.y = __floats2half2_rn(a2 * scale, a3 * scale);
    *(__half2*)&o.z = __floats2half2_rn(a4 * scale, a5 * scale);
    *(__half2*)&o.w = __floats2half2_rn(a6 * scale, a7 * scale);
    cur[(size_t)v * 8 + sub] = o;
}

// ---------------------------------------------------------------------------
// Gate + combine, 8-lane-group layout: 4 nodes/warp, lane owns channels
// [sub*8, sub*8+8). All slices (incl. h0 from g_F16) read as uint4.
// Stored slices are t_k = norm .* h_k, so h_k = t_k / norm.
__global__ void __launch_bounds__(256)
k_gate(const float* __restrict__ s, float* __restrict__ out) {
    int warp = blockIdx.x * 8 + (threadIdx.x >> 5);
    int lane = threadIdx.x & 31;
    int sub  = lane & 7;
    int v    = warp * 4 + (lane >> 3);
    if (v >= NNODES) v = NNODES - 1;

    float rd = 1.0f / g_norm[v];   // sqrt(deg); h_k = t_k * rd (incl. k=0)

    float4 s0 = *(const float4*)(s + sub * 8);
    float4 s1 = *(const float4*)(s + sub * 8 + 4);

    float acc[8] = {0.f, 0.f, 0.f, 0.f, 0.f, 0.f, 0.f, 0.f};

#pragma unroll
    for (int k = 0; k <= KHOPS; k++) {
        const uint4* slice = (const uint4*)(
            (k == 0) ? g_F16 : (g_H + (size_t)(k - 1) * NNODES * 32));
        uint4 raw = slice[(size_t)v * 8 + sub];
        float2 f0 = __half22float2(*(const __half2*)&raw.x);
        float2 f1 = __half22float2(*(const __half2*)&raw.y);
        float2 f2 = __half22float2(*(const __half2*)&raw.z);
        float2 f3 = __half22float2(*(const __half2*)&raw.w);
        float hk[8];
        hk[0] = f0.x * rd; hk[1] = f0.y * rd;
        hk[2] = f1.x * rd; hk[3] = f1.y * rd;
        hk[4] = f2.x * rd; hk[5] = f2.y * rd;
        hk[6] = f3.x * rd; hk[7] = f3.y * rd;

        float p = hk[0] * s0.x + hk[1] * s0.y + hk[2] * s0.z + hk[3] * s0.w +
                  hk[4] * s1.x + hk[5] * s1.y + hk[6] * s1.z + hk[7] * s1.w;
        p += __shfl_xor_sync(0xFFFFFFFFu, p, 1);
        p += __shfl_xor_sync(0xFFFFFFFFu, p, 2);
        p += __shfl_xor_sync(0xFFFFFFFFu, p, 4);
        float g = 1.f / (1.f + __expf(-p));
#pragma unroll
        for (int c = 0; c < 8; c++) acc[c] = fmaf(g, hk[c], acc[c]);
    }

    float4 o0, o1;
    o0.x = acc[0]; o0.y = acc[1]; o0.z = acc[2]; o0.w = acc[3];
    o1.x = acc[4]; o1.y = acc[5]; o1.z = acc[6]; o1.w = acc[7];
    *(float4*)(out + (size_t)v * DIM + sub * 8)     = o0;
    *(float4*)(out + (size_t)v * DIM + sub * 8 + 4) = o1;
}

// ---------------------------------------------------------------------------
extern "C" void kernel_launch(void* const* d_in, const int* in_sizes, int n_in,
                              void* d_out, int out_size) {
    const float* feats = (const float*)d_in[0];
    const float* s     = (const float*)d_in[1];
    const int*   src   = (const int*)d_in[2];
    const int*   dst   = (const int*)d_in[3];
    float*       out   = (float*)d_out;
    int nE = in_sizes[2];

    int nb = (NNODES + SCAN_B - 1) / SCAN_B;       // 98
    int qb = (nE / 4 + 256) / 256;
    int sb = (NNODES + 31) / 32;                   // 3125

    k_zero<<<(NNODES + 255) / 256, 256>>>();
    k_count<<<qb, 256>>>(dst, nE);
    k_scan<<<nb, SCAN_B>>>(feats, nb, nE);
    k_scatter<<<qb, 256>>>(src, dst, nE);

    for (int hop = 0; hop < KHOPS; hop++)
        k_spmm<<<sb, 256>>>(hop);

    k_gate<<<sb, 256>>>(s, out);
}

// round 13
// speedup vs baseline: 1.6279x; 1.0160x over previous
#include <cuda_runtime.h>
#include <cuda_fp16.h>
#include <stdint.h>

// DAGNNConv: 10-hop normalized propagation + sigmoid-gated combination.
// N=100000, D=64, E=1300000 (incl self-loops), K=10.
// R13: CSR replaced by fixed-capacity (64) per-node edge buckets filled
// directly in the count kernel (rank = atomicAdd return). No scan, no
// scatter, no g_rank. Hop inner loop unchanged (scalar accumulators,
// unconditional LDG.128 gathers, pipelined records, norm factored out).

#define NNODES 100000
#define DIM    64
#define KHOPS  10
#define BCAP   64                     // bucket capacity (max in-degree ~35)
#define SCAN_B 1024

__device__ int     g_deg[NNODES];
__device__ float   g_norm[NNODES];
__device__ int     g_bkt[(size_t)NNODES * BCAP];        // edge srcs per dst
__device__ __half2 g_F16[(size_t)NNODES * 32];          // t0 = norm .* feats
__device__ __half2 g_H[(size_t)KHOPS * NNODES * 32];    // t_1..t_10 (scaled)

// ---------------------------------------------------------------------------
__global__ void k_zero() {
    int i = blockIdx.x * blockDim.x + threadIdx.x;
    if (i < NNODES) g_deg[i] = 0;
}

// Fused count + bucket scatter: rank = atomic return; one random store.
__global__ void k_count_scatter(const int* __restrict__ src,
                                const int* __restrict__ dst, int nE) {
    int q = blockIdx.x * blockDim.x + threadIdx.x;
    int nq = nE >> 2;
    if (q < nq) {
        int4 d4 = ((const int4*)dst)[q];
        int4 s4 = ((const int4*)src)[q];
        if ((unsigned)d4.x < NNODES) {
            int r = atomicAdd(&g_deg[d4.x], 1);
            if (r < BCAP) g_bkt[(size_t)d4.x * BCAP + r] = s4.x;
        }
        if ((unsigned)d4.y < NNODES) {
            int r = atomicAdd(&g_deg[d4.y], 1);
            if (r < BCAP) g_bkt[(size_t)d4.y * BCAP + r] = s4.y;
        }
        if ((unsigned)d4.z < NNODES) {
            int r = atomicAdd(&g_deg[d4.z], 1);
            if (r < BCAP) g_bkt[(size_t)d4.z * BCAP + r] = s4.z;
        }
        if ((unsigned)d4.w < NNODES) {
            int r = atomicAdd(&g_deg[d4.w], 1);
            if (r < BCAP) g_bkt[(size_t)d4.w * BCAP + r] = s4.w;
        }
    } else if (q == nq) {
        for (int e = nq * 4; e < nE; e++) {
            unsigned d = (unsigned)dst[e];
            unsigned s = (unsigned)src[e];
            if (d < NNODES) {
                int r = atomicAdd(&g_deg[d], 1);
                if (r < BCAP) g_bkt[(size_t)d * BCAP + r] = (int)s;
            }
        }
    }
}

// norm = deg^-1/2 ; t0 = norm .* feats (fp16). Thread handles 8 channels.
__global__ void k_norm_cvt(const float* __restrict__ feats) {
    int i = blockIdx.x * blockDim.x + threadIdx.x;   // over NNODES*8
    if (i >= NNODES * 8) return;
    int v = i >> 3;
    float nv = rsqrtf((float)g_deg[v]);
    if ((i & 7) == 0) g_norm[v] = nv;
    float4 f0 = *(const float4*)(feats + (size_t)i * 8);
    float4 f1 = *(const float4*)(feats + (size_t)i * 8 + 4);
    uint4 o;
    *(__half2*)&o.x = __floats2half2_rn(f0.x * nv, f0.y * nv);
    *(__half2*)&o.y = __floats2half2_rn(f0.z * nv, f0.w * nv);
    *(__half2*)&o.z = __floats2half2_rn(f1.x * nv, f1.y * nv);
    *(__half2*)&o.w = __floats2half2_rn(f1.z * nv, f1.w * nv);
    ((uint4*)g_F16)[i] = o;
}

// ---------------------------------------------------------------------------
// One hop: t_cur[v] = norm[v]^2 * sum_{u->v} t_prev[u].
// Block owns 32 consecutive nodes, rank-sorted by degree in smem; each warp
// takes 4 rank-adjacent nodes; 8 lanes/node; lane owns 8 channels (16B).
// Edge records live at g_bkt[v*64 ...], count in g_deg[v].
__global__ void __launch_bounds__(256)
k_spmm(int hop) {
    __shared__ int sdeg[32], sperm[32];
    int tid = threadIdx.x;
    int blockBase = blockIdx.x * 32;

    if (tid < 32) {
        int v = blockBase + tid;
        if (v >= NNODES) v = NNODES - 1;
        int d = g_deg[v];
        sdeg[tid] = (d < BCAP) ? d : BCAP;
    }
    __syncthreads();
    if (tid < 32) {
        int d = sdeg[tid];
        int r = 0;
#pragma unroll
        for (int j = 0; j < 32; j++) {
            int dj = sdeg[j];
            r += (dj > d) || (dj == d && j < tid);
        }
        sperm[r] = tid;   // descending degree
    }
    __syncthreads();

    int lane = tid & 31;
    int sub  = lane & 7;
    int gb   = lane & 24;
    int slot = (tid >> 5) * 4 + (lane >> 3);
    int local = sperm[slot];
    int v = blockBase + local;
    if (v >= NNODES) v = NNODES - 1;
    int deg = sdeg[local];
    const int* __restrict__ row = g_bkt + (size_t)v * BCAP;

    const uint4* __restrict__ prev = (const uint4*)(
        (hop == 0) ? g_F16 : (g_H + (size_t)(hop - 1) * NNODES * 32));
    uint4* __restrict__ cur = (uint4*)(g_H + (size_t)hop * NNODES * 32);

    float nrm = g_norm[v];
    float scale = nrm * nrm;

    int maxdeg = deg;
#pragma unroll
    for (int o = 16; o; o >>= 1)
        maxdeg = max(maxdeg, __shfl_xor_sync(0xFFFFFFFFu, maxdeg, o));
    int nbatch = (maxdeg + 7) >> 3;

    float a0 = 0.f, a1 = 0.f, a2 = 0.f, a3 = 0.f;
    float a4 = 0.f, a5 = 0.f, a6 = 0.f, a7 = 0.f;

    int er = (sub < deg) ? row[sub] : 0;

    for (int b = 0; b < nbatch; b++) {
        int er_next = 0;
        int nidx = (b + 1) * 8 + sub;
        if (b + 1 < nbatch && nidx < deg) er_next = row[nidx];

        int base = b * 8;
        int srcs[8];
#pragma unroll
        for (int j = 0; j < 8; j++)
            srcs[j] = __shfl_sync(0xFFFFFFFFu, er, gb + j);

        uint4 raws[8];
#pragma unroll
        for (int j = 0; j < 8; j++)
            raws[j] = prev[(size_t)srcs[j] * 8 + sub];
#pragma unroll
        for (int j = 0; j < 8; j++) {
            float w = (base + j < deg) ? 1.f : 0.f;
            float2 f0 = __half22float2(*(const __half2*)&raws[j].x);
            float2 f1 = __half22float2(*(const __half2*)&raws[j].y);
            float2 f2 = __half22float2(*(const __half2*)&raws[j].z);
            float2 f3 = __half22float2(*(const __half2*)&raws[j].w);
            a0 = fmaf(w, f0.x, a0); a1 = fmaf(w, f0.y, a1);
            a2 = fmaf(w, f1.x, a2); a3 = fmaf(w, f1.y, a3);
            a4 = fmaf(w, f2.x, a4); a5 = fmaf(w, f2.y, a5);
            a6 = fmaf(w, f3.x, a6); a7 = fmaf(w, f3.y, a7);
        }
        er = er_next;
    }

    uint4 o;
    *(__half2*)&o.x = __floats2half2_rn(a0 * scale, a1 * scale);
    *(__half2*)&o.y = __floats2half2_rn(a2 * scale, a3 * scale);
    *(__half2*)&o.z = __floats2half2_rn(a4 * scale, a5 * scale);
    *(__half2*)&o.w = __floats2half2_rn(a6 * scale, a7 * scale);
    cur[(size_t)v * 8 + sub] = o;
}

// ---------------------------------------------------------------------------
// Gate + combine, 8-lane-group layout: 4 nodes/warp, lane owns channels
// [sub*8, sub*8+8). All slices (incl. h0 from g_F16) read as uint4.
// Stored slices are t_k = norm .* h_k, so h_k = t_k / norm.
__global__ void __launch_bounds__(256)
k_gate(const float* __restrict__ s, float* __restrict__ out) {
    int warp = blockIdx.x * 8 + (threadIdx.x >> 5);
    int lane = threadIdx.x & 31;
    int sub  = lane & 7;
    int v    = warp * 4 + (lane >> 3);
    if (v >= NNODES) v = NNODES - 1;

    float rd = 1.0f / g_norm[v];   // sqrt(deg); h_k = t_k * rd (incl. k=0)

    float4 s0 = *(const float4*)(s + sub * 8);
    float4 s1 = *(const float4*)(s + sub * 8 + 4);

    float acc[8] = {0.f, 0.f, 0.f, 0.f, 0.f, 0.f, 0.f, 0.f};

#pragma unroll
    for (int k = 0; k <= KHOPS; k++) {
        const uint4* slice = (const uint4*)(
            (k == 0) ? g_F16 : (g_H + (size_t)(k - 1) * NNODES * 32));
        uint4 raw = slice[(size_t)v * 8 + sub];
        float2 f0 = __half22float2(*(const __half2*)&raw.x);
        float2 f1 = __half22float2(*(const __half2*)&raw.y);
        float2 f2 = __half22float2(*(const __half2*)&raw.z);
        float2 f3 = __half22float2(*(const __half2*)&raw.w);
        float hk[8];
        hk[0] = f0.x * rd; hk[1] = f0.y * rd;
        hk[2] = f1.x * rd; hk[3] = f1.y * rd;
        hk[4] = f2.x * rd; hk[5] = f2.y * rd;
        hk[6] = f3.x * rd; hk[7] = f3.y * rd;

        float p = hk[0] * s0.x + hk[1] * s0.y + hk[2] * s0.z + hk[3] * s0.w +
                  hk[4] * s1.x + hk[5] * s1.y + hk[6] * s1.z + hk[7] * s1.w;
        p += __shfl_xor_sync(0xFFFFFFFFu, p, 1);
        p += __shfl_xor_sync(0xFFFFFFFFu, p, 2);
        p += __shfl_xor_sync(0xFFFFFFFFu, p, 4);
        float g = 1.f / (1.f + __expf(-p));
#pragma unroll
        for (int c = 0; c < 8; c++) acc[c] = fmaf(g, hk[c], acc[c]);
    }

    float4 o0, o1;
    o0.x = acc[0]; o0.y = acc[1]; o0.z = acc[2]; o0.w = acc[3];
    o1.x = acc[4]; o1.y = acc[5]; o1.z = acc[6]; o1.w = acc[7];
    *(float4*)(out + (size_t)v * DIM + sub * 8)     = o0;
    *(float4*)(out + (size_t)v * DIM + sub * 8 + 4) = o1;
}

// ---------------------------------------------------------------------------
extern "C" void kernel_launch(void* const* d_in, const int* in_sizes, int n_in,
                              void* d_out, int out_size) {
    const float* feats = (const float*)d_in[0];
    const float* s     = (const float*)d_in[1];
    const int*   src   = (const int*)d_in[2];
    const int*   dst   = (const int*)d_in[3];
    float*       out   = (float*)d_out;
    int nE = in_sizes[2];

    int qb = (nE / 4 + 256) / 256;
    int sb = (NNODES + 31) / 32;                   // 3125

    k_zero<<<(NNODES + 255) / 256, 256>>>();
    k_count_scatter<<<qb, 256>>>(src, dst, nE);
    k_norm_cvt<<<(NNODES * 8 + 255) / 256, 256>>>(feats);

    for (int hop = 0; hop < KHOPS; hop++)
        k_spmm<<<sb, 256>>>(hop);

    k_gate<<<sb, 256>>>(s, out);
}

// round 14
// speedup vs baseline: 1.7344x; 1.0654x over previous
#include <cuda_runtime.h>
#include <cuda_fp16.h>
#include <stdint.h>

// DAGNNConv: 10-hop normalized propagation + sigmoid-gated combination.
// N=100000, D=64, E=1300000 (incl self-loops), K=10.
// R14: hop loop de-instruction-ified — zero-row padding (phantom row at
// index NNODES, never written => stays zero) kills all per-edge predicates;
// fp16 pairwise HADD2 pre-reduction halves convert+accumulate ops; 32-bit
// gather indices. Bucket build (R13) unchanged.

#define NNODES 100000
#define DIM    64
#define KHOPS  10
#define BCAP   64
#define NROWS  (NNODES + 1)           // +1 phantom zero row

__device__ int     g_deg[NNODES];
__device__ float   g_norm[NNODES];
__device__ int     g_bkt[(size_t)NNODES * BCAP];        // edge srcs per dst
__device__ __half2 g_F16[(size_t)NROWS * 32];           // t0 = norm .* feats
__device__ __half2 g_H[(size_t)KHOPS * NROWS * 32];     // t_1..t_10 (scaled)

// ---------------------------------------------------------------------------
__global__ void k_zero() {
    int i = blockIdx.x * blockDim.x + threadIdx.x;
    if (i < NNODES) g_deg[i] = 0;
}

// Fused count + bucket scatter: rank = atomic return; one random store.
__global__ void k_count_scatter(const int* __restrict__ src,
                                const int* __restrict__ dst, int nE) {
    int q = blockIdx.x * blockDim.x + threadIdx.x;
    int nq = nE >> 2;
    if (q < nq) {
        int4 d4 = ((const int4*)dst)[q];
        int4 s4 = ((const int4*)src)[q];
        if ((unsigned)d4.x < NNODES) {
            int r = atomicAdd(&g_deg[d4.x], 1);
            if (r < BCAP) g_bkt[(size_t)d4.x * BCAP + r] = s4.x;
        }
        if ((unsigned)d4.y < NNODES) {
            int r = atomicAdd(&g_deg[d4.y], 1);
            if (r < BCAP) g_bkt[(size_t)d4.y * BCAP + r] = s4.y;
        }
        if ((unsigned)d4.z < NNODES) {
            int r = atomicAdd(&g_deg[d4.z], 1);
            if (r < BCAP) g_bkt[(size_t)d4.z * BCAP + r] = s4.z;
        }
        if ((unsigned)d4.w < NNODES) {
            int r = atomicAdd(&g_deg[d4.w], 1);
            if (r < BCAP) g_bkt[(size_t)d4.w * BCAP + r] = s4.w;
        }
    } else if (q == nq) {
        for (int e = nq * 4; e < nE; e++) {
            unsigned d = (unsigned)dst[e];
            unsigned s = (unsigned)src[e];
            if (d < NNODES) {
                int r = atomicAdd(&g_deg[d], 1);
                if (r < BCAP) g_bkt[(size_t)d * BCAP + r] = (int)s;
            }
        }
    }
}

// norm = deg^-1/2 ; t0 = norm .* feats (fp16). Thread handles 8 channels.
__global__ void k_norm_cvt(const float* __restrict__ feats) {
    int i = blockIdx.x * blockDim.x + threadIdx.x;   // over NNODES*8
    if (i >= NNODES * 8) return;
    int v = i >> 3;
    float nv = rsqrtf((float)g_deg[v]);
    if ((i & 7) == 0) g_norm[v] = nv;
    float4 f0 = *(const float4*)(feats + (size_t)i * 8);
    float4 f1 = *(const float4*)(feats + (size_t)i * 8 + 4);
    uint4 o;
    *(__half2*)&o.x = __floats2half2_rn(f0.x * nv, f0.y * nv);
    *(__half2*)&o.y = __floats2half2_rn(f0.z * nv, f0.w * nv);
    *(__half2*)&o.z = __floats2half2_rn(f1.x * nv, f1.y * nv);
    *(__half2*)&o.w = __floats2half2_rn(f1.z * nv, f1.w * nv);
    ((uint4*)g_F16)[i] = o;
}

// ---------------------------------------------------------------------------
// One hop: t_cur[v] = norm[v]^2 * sum_{u->v} t_prev[u].
// Block owns 32 consecutive nodes, rank-sorted by degree in smem; warp takes
// 4 rank-adjacent nodes; 8 lanes/node; lane owns 8 channels (16B gathers).
// Padded slots gather the phantom zero row -> unconditional accumulate.
// Pairs of edges pre-summed in fp16 (HADD2) before fp32 accumulation.
__global__ void __launch_bounds__(256)
k_spmm(int hop) {
    __shared__ int sdeg[32], sperm[32];
    int tid = threadIdx.x;
    int blockBase = blockIdx.x * 32;

    if (tid < 32) {
        int v = blockBase + tid;
        if (v >= NNODES) v = NNODES - 1;
        int d = g_deg[v];
        sdeg[tid] = (d < BCAP) ? d : BCAP;
    }
    __syncthreads();
    if (tid < 32) {
        int d = sdeg[tid];
        int r = 0;
#pragma unroll
        for (int j = 0; j < 32; j++) {
            int dj = sdeg[j];
            r += (dj > d) || (dj == d && j < tid);
        }
        sperm[r] = tid;   // descending degree
    }
    __syncthreads();

    int lane = tid & 31;
    int sub  = lane & 7;
    int gb   = lane & 24;
    int slot = (tid >> 5) * 4 + (lane >> 3);
    int local = sperm[slot];
    int v = blockBase + local;
    if (v >= NNODES) v = NNODES - 1;
    int deg = sdeg[local];
    const int* __restrict__ row = g_bkt + (size_t)v * BCAP;

    const uint4* __restrict__ prev = (const uint4*)(
        (hop == 0) ? g_F16 : (g_H + (size_t)(hop - 1) * NROWS * 32));
    uint4* __restrict__ cur = (uint4*)(g_H + (size_t)hop * NROWS * 32);

    float nrm = g_norm[v];
    float scale = nrm * nrm;

    int maxdeg = deg;
#pragma unroll
    for (int o = 16; o; o >>= 1)
        maxdeg = max(maxdeg, __shfl_xor_sync(0xFFFFFFFFu, maxdeg, o));
    int nbatch = (maxdeg + 7) >> 3;

    float a0 = 0.f, a1 = 0.f, a2 = 0.f, a3 = 0.f;
    float a4 = 0.f, a5 = 0.f, a6 = 0.f, a7 = 0.f;

    // this lane's record for batch 0; padded lanes -> phantom zero row
    int er = (sub < deg) ? row[sub] : NNODES;

    for (int b = 0; b < nbatch; b++) {
        int er_next = NNODES;
        int nidx = (b + 1) * 8 + sub;
        if (b + 1 < nbatch && nidx < deg) er_next = row[nidx];

        int idxs[8];
#pragma unroll
        for (int j = 0; j < 8; j++)
            idxs[j] = __shfl_sync(0xFFFFFFFFu, er, gb + j) * 8 + sub;

        uint4 raws[8];
#pragma unroll
        for (int j = 0; j < 8; j++)
            raws[j] = prev[idxs[j]];

        // pairwise fp16 pre-reduction, then fp32 accumulate
#pragma unroll
        for (int p = 0; p < 4; p++) {
            __half2 hx = __hadd2(*(const __half2*)&raws[2*p].x,
                                 *(const __half2*)&raws[2*p+1].x);
            __half2 hy = __hadd2(*(const __half2*)&raws[2*p].y,
                                 *(const __half2*)&raws[2*p+1].y);
            __half2 hz = __hadd2(*(const __half2*)&raws[2*p].z,
                                 *(const __half2*)&raws[2*p+1].z);
            __half2 hw = __hadd2(*(const __half2*)&raws[2*p].w,
                                 *(const __half2*)&raws[2*p+1].w);
            float2 fx = __half22float2(hx);
            float2 fy = __half22float2(hy);
            float2 fz = __half22float2(hz);
            float2 fw = __half22float2(hw);
            a0 += fx.x; a1 += fx.y;
            a2 += fy.x; a3 += fy.y;
            a4 += fz.x; a5 += fz.y;
            a6 += fw.x; a7 += fw.y;
        }
        er = er_next;
    }

    uint4 o;
    *(__half2*)&o.x = __floats2half2_rn(a0 * scale, a1 * scale);
    *(__half2*)&o.y = __floats2half2_rn(a2 * scale, a3 * scale);
    *(__half2*)&o.z = __floats2half2_rn(a4 * scale, a5 * scale);
    *(__half2*)&o.w = __floats2half2_rn(a6 * scale, a7 * scale);
    cur[v * 8 + sub] = o;
}

// ---------------------------------------------------------------------------
// Gate + combine, 8-lane-group layout: 4 nodes/warp, lane owns channels
// [sub*8, sub*8+8). All slices (incl. h0 from g_F16) read as uint4.
// Stored slices are t_k = norm .* h_k, so h_k = t_k / norm.
__global__ void __launch_bounds__(256)
k_gate(const float* __restrict__ s, float* __restrict__ out) {
    int warp = blockIdx.x * 8 + (threadIdx.x >> 5);
    int lane = threadIdx.x & 31;
    int sub  = lane & 7;
    int v    = warp * 4 + (lane >> 3);
    if (v >= NNODES) v = NNODES - 1;

    float rd = 1.0f / g_norm[v];   // sqrt(deg); h_k = t_k * rd (incl. k=0)

    float4 s0 = *(const float4*)(s + sub * 8);
    float4 s1 = *(const float4*)(s + sub * 8 + 4);

    float acc[8] = {0.f, 0.f, 0.f, 0.f, 0.f, 0.f, 0.f, 0.f};

#pragma unroll
    for (int k = 0; k <= KHOPS; k++) {
        const uint4* slice = (const uint4*)(
            (k == 0) ? g_F16 : (g_H + (size_t)(k - 1) * NROWS * 32));
        uint4 raw = slice[v * 8 + sub];
        float2 f0 = __half22float2(*(const __half2*)&raw.x);
        float2 f1 = __half22float2(*(const __half2*)&raw.y);
        float2 f2 = __half22float2(*(const __half2*)&raw.z);
        float2 f3 = __half22float2(*(const __half2*)&raw.w);
        float hk[8];
        hk[0] = f0.x * rd; hk[1] = f0.y * rd;
        hk[2] = f1.x * rd; hk[3] = f1.y * rd;
        hk[4] = f2.x * rd; hk[5] = f2.y * rd;
        hk[6] = f3.x * rd; hk[7] = f3.y * rd;

        float p = hk[0] * s0.x + hk[1] * s0.y + hk[2] * s0.z + hk[3] * s0.w +
                  hk[4] * s1.x + hk[5] * s1.y + hk[6] * s1.z + hk[7] * s1.w;
        p += __shfl_xor_sync(0xFFFFFFFFu, p, 1);
        p += __shfl_xor_sync(0xFFFFFFFFu, p, 2);
        p += __shfl_xor_sync(0xFFFFFFFFu, p, 4);
        float g = 1.f / (1.f + __expf(-p));
#pragma unroll
        for (int c = 0; c < 8; c++) acc[c] = fmaf(g, hk[c], acc[c]);
    }

    float4 o0, o1;
    o0.x = acc[0]; o0.y = acc[1]; o0.z = acc[2]; o0.w = acc[3];
    o1.x = acc[4]; o1.y = acc[5]; o1.z = acc[6]; o1.w = acc[7];
    *(float4*)(out + (size_t)v * DIM + sub * 8)     = o0;
    *(float4*)(out + (size_t)v * DIM + sub * 8 + 4) = o1;
}

// ---------------------------------------------------------------------------
extern "C" void kernel_launch(void* const* d_in, const int* in_sizes, int n_in,
                              void* d_out, int out_size) {
    const float* feats = (const float*)d_in[0];
    const float* s     = (const float*)d_in[1];
    const int*   src   = (const int*)d_in[2];
    const int*   dst   = (const int*)d_in[3];
    float*       out   = (float*)d_out;
    int nE = in_sizes[2];

    int qb = (nE / 4 + 256) / 256;
    int sb = (NNODES + 31) / 32;                   // 3125

    k_zero<<<(NNODES + 255) / 256, 256>>>();
    k_count_scatter<<<qb, 256>>>(src, dst, nE);
    k_norm_cvt<<<(NNODES * 8 + 255) / 256, 256>>>(feats);

    for (int hop = 0; hop < KHOPS; hop++)
        k_spmm<<<sb, 256>>>(hop);

    k_gate<<<sb, 256>>>(s, out);
}

// round 15
// speedup vs baseline: 1.8512x; 1.0673x over previous
#include <cuda_runtime.h>
#include <cuda_fp16.h>
#include <stdint.h>

// DAGNNConv: 10-hop normalized propagation + sigmoid-gated combination.
// N=100000, D=64, E=1300000 (incl self-loops), K=10.
// R15: gate fused into 10th hop as a SEPARATE kernel (verbatim hop body +
// scalar epilogue; hops 0..8 untouched). Deeper fp16 tree (8->4->2).
// maxdeg from sort rank. Bucket build (R13/R14) unchanged.

#define NNODES 100000
#define DIM    64
#define KHOPS  10
#define BCAP   64
#define NROWS  (NNODES + 1)           // +1 phantom zero row

__device__ int     g_deg[NNODES];
__device__ float   g_norm[NNODES];
__device__ int     g_bkt[(size_t)NNODES * BCAP];        // edge srcs per dst
__device__ __half2 g_F16[(size_t)NROWS * 32];           // t0 = norm .* feats
__device__ __half2 g_H[(size_t)(KHOPS - 1) * NROWS * 32]; // t_1..t_9

// ---------------------------------------------------------------------------
__global__ void k_zero() {
    int i = blockIdx.x * blockDim.x + threadIdx.x;
    if (i < NNODES) g_deg[i] = 0;
}

__global__ void k_count_scatter(const int* __restrict__ src,
                                const int* __restrict__ dst, int nE) {
    int q = blockIdx.x * blockDim.x + threadIdx.x;
    int nq = nE >> 2;
    if (q < nq) {
        int4 d4 = ((const int4*)dst)[q];
        int4 s4 = ((const int4*)src)[q];
        if ((unsigned)d4.x < NNODES) {
            int r = atomicAdd(&g_deg[d4.x], 1);
            if (r < BCAP) g_bkt[(size_t)d4.x * BCAP + r] = s4.x;
        }
        if ((unsigned)d4.y < NNODES) {
            int r = atomicAdd(&g_deg[d4.y], 1);
            if (r < BCAP) g_bkt[(size_t)d4.y * BCAP + r] = s4.y;
        }
        if ((unsigned)d4.z < NNODES) {
            int r = atomicAdd(&g_deg[d4.z], 1);
            if (r < BCAP) g_bkt[(size_t)d4.z * BCAP + r] = s4.z;
        }
        if ((unsigned)d4.w < NNODES) {
            int r = atomicAdd(&g_deg[d4.w], 1);
            if (r < BCAP) g_bkt[(size_t)d4.w * BCAP + r] = s4.w;
        }
    } else if (q == nq) {
        for (int e = nq * 4; e < nE; e++) {
            unsigned d = (unsigned)dst[e];
            unsigned s = (unsigned)src[e];
            if (d < NNODES) {
                int r = atomicAdd(&g_deg[d], 1);
                if (r < BCAP) g_bkt[(size_t)d * BCAP + r] = (int)s;
            }
        }
    }
}

__global__ void k_norm_cvt(const float* __restrict__ feats) {
    int i = blockIdx.x * blockDim.x + threadIdx.x;   // over NNODES*8
    if (i >= NNODES * 8) return;
    int v = i >> 3;
    float nv = rsqrtf((float)g_deg[v]);
    if ((i & 7) == 0) g_norm[v] = nv;
    float4 f0 = *(const float4*)(feats + (size_t)i * 8);
    float4 f1 = *(const float4*)(feats + (size_t)i * 8 + 4);
    uint4 o;
    *(__half2*)&o.x = __floats2half2_rn(f0.x * nv, f0.y * nv);
    *(__half2*)&o.y = __floats2half2_rn(f0.z * nv, f0.w * nv);
    *(__half2*)&o.z = __floats2half2_rn(f1.x * nv, f1.y * nv);
    *(__half2*)&o.w = __floats2half2_rn(f1.z * nv, f1.w * nv);
    ((uint4*)g_F16)[i] = o;
}

// ---------------------------------------------------------------------------
// Shared prologue macro body (kept textual to avoid helper-function regs).
// Hop body: block owns 32 nodes, rank-sorted by degree; warp takes 4
// rank-adjacent nodes; 8 lanes/node; lane owns 8 channels. Padded slots
// gather the phantom zero row. fp16 tree 8->4->2, fp32 accumulate.

#define SPMM_PROLOGUE                                                        \
    __shared__ int sdeg[32], sperm[32];                                      \
    int tid = threadIdx.x;                                                   \
    int blockBase = blockIdx.x * 32;                                         \
    if (tid < 32) {                                                          \
        int v = blockBase + tid;                                             \
        if (v >= NNODES) v = NNODES - 1;                                     \
        int d = g_deg[v];                                                    \
        sdeg[tid] = (d < BCAP) ? d : BCAP;                                   \
    }                                                                        \
    __syncthreads();                                                         \
    if (tid < 32) {                                                          \
        int d = sdeg[tid];                                                   \
        int r = 0;                                                           \
        _Pragma("unroll")                                                    \
        for (int j = 0; j < 32; j++) {                                       \
            int dj = sdeg[j];                                                \
            r += (dj > d) || (dj == d && j < tid);                           \
        }                                                                    \
        sperm[r] = tid;                                                      \
    }                                                                        \
    __syncthreads();                                                         \
    int lane = tid & 31;                                                     \
    int sub  = lane & 7;                                                     \
    int gb   = lane & 24;                                                    \
    int slot = (tid >> 5) * 4 + (lane >> 3);                                 \
    int local = sperm[slot];                                                 \
    int v = blockBase + local;                                               \
    if (v >= NNODES) v = NNODES - 1;                                         \
    int deg = sdeg[local];                                                   \
    int maxdeg = sdeg[sperm[(tid >> 5) * 4]];                                \
    const int* __restrict__ row = g_bkt + (size_t)v * BCAP;                  \
    float nrm = g_norm[v];                                                   \
    float scale = nrm * nrm;                                                 \
    int nbatch = (maxdeg + 7) >> 3;                                          \
    float a0 = 0.f, a1 = 0.f, a2 = 0.f, a3 = 0.f;                            \
    float a4 = 0.f, a5 = 0.f, a6 = 0.f, a7 = 0.f;                            \
    int er = (sub < deg) ? row[sub] : NNODES;                                \
    for (int b = 0; b < nbatch; b++) {                                       \
        int er_next = NNODES;                                                \
        int nidx = (b + 1) * 8 + sub;                                        \
        if (b + 1 < nbatch && nidx < deg) er_next = row[nidx];               \
        int idxs[8];                                                         \
        _Pragma("unroll")                                                    \
        for (int j = 0; j < 8; j++)                                          \
            idxs[j] = __shfl_sync(0xFFFFFFFFu, er, gb + j) * 8 + sub;        \
        uint4 raws[8];                                                       \
        _Pragma("unroll")                                                    \
        for (int j = 0; j < 8; j++)                                          \
            raws[j] = prev[idxs[j]];                                         \
        uint4 m0, m1;                                                        \
        _Pragma("unroll")                                                    \
        for (int p = 0; p < 2; p++) {                                        \
            uint4* mp = p ? &m1 : &m0;                                       \
            __half2 hx = __hadd2(__hadd2(*(const __half2*)&raws[4*p].x,      \
                                         *(const __half2*)&raws[4*p+1].x),  \
                                 __hadd2(*(const __half2*)&raws[4*p+2].x,    \
                                         *(const __half2*)&raws[4*p+3].x)); \
            __half2 hy = __hadd2(__hadd2(*(const __half2*)&raws[4*p].y,      \
                                         *(const __half2*)&raws[4*p+1].y),  \
                                 __hadd2(*(const __half2*)&raws[4*p+2].y,    \
                                         *(const __half2*)&raws[4*p+3].y)); \
            __half2 hz = __hadd2(__hadd2(*(const __half2*)&raws[4*p].z,      \
                                         *(const __half2*)&raws[4*p+1].z),  \
                                 __hadd2(*(const __half2*)&raws[4*p+2].z,    \
                                         *(const __half2*)&raws[4*p+3].z)); \
            __half2 hw = __hadd2(__hadd2(*(const __half2*)&raws[4*p].w,      \
                                         *(const __half2*)&raws[4*p+1].w),  \
                                 __hadd2(*(const __half2*)&raws[4*p+2].w,    \
                                         *(const __half2*)&raws[4*p+3].w)); \
            *(__half2*)&mp->x = hx; *(__half2*)&mp->y = hy;                  \
            *(__half2*)&mp->z = hz; *(__half2*)&mp->w = hw;                  \
        }                                                                    \
        {                                                                    \
            float2 fx0 = __half22float2(*(const __half2*)&m0.x);             \
            float2 fy0 = __half22float2(*(const __half2*)&m0.y);             \
            float2 fz0 = __half22float2(*(const __half2*)&m0.z);             \
            float2 fw0 = __half22float2(*(const __half2*)&m0.w);             \
            float2 fx1 = __half22float2(*(const __half2*)&m1.x);             \
            float2 fy1 = __half22float2(*(const __half2*)&m1.y);             \
            float2 fz1 = __half22float2(*(const __half2*)&m1.z);             \
            float2 fw1 = __half22float2(*(const __half2*)&m1.w);             \
            a0 += fx0.x + fx1.x; a1 += fx0.y + fx1.y;                        \
            a2 += fy0.x + fy1.x; a3 += fy0.y + fy1.y;                        \
            a4 += fz0.x + fz1.x; a5 += fz0.y + fz1.y;                        \
            a6 += fw0.x + fw1.x; a7 += fw0.y + fw1.y;                        \
        }                                                                    \
        er = er_next;                                                        \
    }

// Hops 0..8: store t fp16.
__global__ void __launch_bounds__(256)
k_spmm(int hop) {
    const uint4* __restrict__ prev = (const uint4*)(
        (hop == 0) ? g_F16 : (g_H + (size_t)(hop - 1) * NROWS * 32));
    uint4* __restrict__ cur = (uint4*)(g_H + (size_t)hop * NROWS * 32);
    SPMM_PROLOGUE
    uint4 o;
    *(__half2*)&o.x = __floats2half2_rn(a0 * scale, a1 * scale);
    *(__half2*)&o.y = __floats2half2_rn(a2 * scale, a3 * scale);
    *(__half2*)&o.z = __floats2half2_rn(a4 * scale, a5 * scale);
    *(__half2*)&o.w = __floats2half2_rn(a6 * scale, a7 * scale);
    cur[v * 8 + sub] = o;
}

// Hop 9 (the 10th) + fused gate: h10 = a * nrm from registers; slices
// k=0..9 from fp16 buffers (h_k = t_k / nrm).
__global__ void __launch_bounds__(256)
k_spmm_last(const float* __restrict__ s, float* __restrict__ out) {
    const uint4* __restrict__ prev =
        (const uint4*)(g_H + (size_t)(KHOPS - 2) * NROWS * 32);
    SPMM_PROLOGUE

    float rd = 1.0f / nrm;
    float4 s0 = *(const float4*)(s + sub * 8);
    float4 s1 = *(const float4*)(s + sub * 8 + 4);

    float c0 = 0.f, c1 = 0.f, c2 = 0.f, c3 = 0.f;
    float c4 = 0.f, c5 = 0.f, c6 = 0.f, c7 = 0.f;

#pragma unroll
    for (int k = 0; k <= KHOPS; k++) {
        float h0, h1, h2, h3, h4, h5, h6, h7;
        if (k < KHOPS) {
            const uint4* slice = (const uint4*)(
                (k == 0) ? g_F16 : (g_H + (size_t)(k - 1) * NROWS * 32));
            uint4 raw = slice[v * 8 + sub];
            float2 f0 = __half22float2(*(const __half2*)&raw.x);
            float2 f1 = __half22float2(*(const __half2*)&raw.y);
            float2 f2 = __half22float2(*(const __half2*)&raw.z);
            float2 f3 = __half22float2(*(const __half2*)&raw.w);
            h0 = f0.x * rd; h1 = f0.y * rd;
            h2 = f1.x * rd; h3 = f1.y * rd;
            h4 = f2.x * rd; h5 = f2.y * rd;
            h6 = f3.x * rd; h7 = f3.y * rd;
        } else {
            h0 = a0 * nrm; h1 = a1 * nrm; h2 = a2 * nrm; h3 = a3 * nrm;
            h4 = a4 * nrm; h5 = a5 * nrm; h6 = a6 * nrm; h7 = a7 * nrm;
        }
        float p = h0 * s0.x + h1 * s0.y + h2 * s0.z + h3 * s0.w +
                  h4 * s1.x + h5 * s1.y + h6 * s1.z + h7 * s1.w;
        p += __shfl_xor_sync(0xFFFFFFFFu, p, 1);
        p += __shfl_xor_sync(0xFFFFFFFFu, p, 2);
        p += __shfl_xor_sync(0xFFFFFFFFu, p, 4);
        float g = 1.f / (1.f + __expf(-p));
        c0 = fmaf(g, h0, c0); c1 = fmaf(g, h1, c1);
        c2 = fmaf(g, h2, c2); c3 = fmaf(g, h3, c3);
        c4 = fmaf(g, h4, c4); c5 = fmaf(g, h5, c5);
        c6 = fmaf(g, h6, c6); c7 = fmaf(g, h7, c7);
    }

    float4 o0, o1;
    o0.x = c0; o0.y = c1; o0.z = c2; o0.w = c3;
    o1.x = c4; o1.y = c5; o1.z = c6; o1.w = c7;
    *(float4*)(out + (size_t)v * DIM + sub * 8)     = o0;
    *(float4*)(out + (size_t)v * DIM + sub * 8 + 4) = o1;
}

// ---------------------------------------------------------------------------
extern "C" void kernel_launch(void* const* d_in, const int* in_sizes, int n_in,
                              void* d_out, int out_size) {
    const float* feats = (const float*)d_in[0];
    const float* s     = (const float*)d_in[1];
    const int*   src   = (const int*)d_in[2];
    const int*   dst   = (const int*)d_in[3];
    float*       out   = (float*)d_out;
    int nE = in_sizes[2];

    int qb = (nE / 4 + 256) / 256;
    int sb = (NNODES + 31) / 32;                   // 3125

    k_zero<<<(NNODES + 255) / 256, 256>>>();
    k_count_scatter<<<qb, 256>>>(src, dst, nE);
    k_norm_cvt<<<(NNODES * 8 + 255) / 256, 256>>>(feats);

    for (int hop = 0; hop < KHOPS - 1; hop++)
        k_spmm<<<sb, 256>>>(hop);

    k_spmm_last<<<sb, 256>>>(s, out);
}